// round 7
// baseline (speedup 1.0000x reference)
#include <cuda_runtime.h>
#include <cuda_bf16.h>
#include <math.h>
#include <stdint.h>

// Problem dims (fixed)
#define BB 8
#define MM 2048
#define DD 1024
#define HALF_D 512
#define ROWS 16384           // BB*MM

// ---------------------------------------------------------------------------
// Device-global scratch (allocation-free, graph-capture safe)
// 2-segment storage: [hi | lo], each K wide. GEMM synthesizes the 3-segment
// schedule A:[hi,lo,hi] x B:[hi,hi,lo] via chunk offset mapping.
// ---------------------------------------------------------------------------
__device__ __nv_bfloat16 g_x2[(size_t)ROWS * 2 * DD];      // x  [hi|lo]
__device__ __nv_bfloat16 g_w2[(size_t)(3 * DD) * 2 * DD];  // [wq;wk;wv] [hi|lo]
__device__ float g_Vf[(size_t)ROWS * DD];
__device__ __nv_bfloat16 g_Q2[(size_t)ROWS * 2 * DD];      // rotated Q [hi|lo]
__device__ __nv_bfloat16 g_K2[(size_t)ROWS * 2 * DD];      // rotated K [hi|lo]
__device__ __nv_bfloat16 g_V2T[(size_t)BB * DD * 2 * MM];  // V^T [hi|lo]
__device__ float g_Sf[(size_t)BB * MM * MM];               // scores fp32
__device__ __nv_bfloat16 g_S2[(size_t)BB * MM * 2 * MM];   // attn [hi|lo]
__device__ float g_cos[(size_t)MM * HALF_D];
__device__ float g_sin[(size_t)MM * HALF_D];

// ---------------------------------------------------------------------------
// PTX helpers (base-ISA: mma.sync / ldmatrix / cp.async)
// ---------------------------------------------------------------------------
__device__ __forceinline__ uint32_t smem_u32(const void* p) {
    uint32_t a;
    asm("{ .reg .u64 t; cvta.to.shared.u64 t, %1; cvt.u32.u64 %0, t; }" : "=r"(a) : "l"(p));
    return a;
}
__device__ __forceinline__ void mma16816(float* d, const uint32_t* a, const uint32_t* b) {
    asm volatile(
        "mma.sync.aligned.m16n8k16.row.col.f32.bf16.bf16.f32 "
        "{%0,%1,%2,%3}, {%4,%5,%6,%7}, {%8,%9}, {%0,%1,%2,%3};"
        : "+f"(d[0]), "+f"(d[1]), "+f"(d[2]), "+f"(d[3])
        : "r"(a[0]), "r"(a[1]), "r"(a[2]), "r"(a[3]), "r"(b[0]), "r"(b[1]));
}
__device__ __forceinline__ void ldsm4(uint32_t* r, uint32_t addr) {
    asm volatile("ldmatrix.sync.aligned.m8n8.x4.shared.b16 {%0,%1,%2,%3}, [%4];"
                 : "=r"(r[0]), "=r"(r[1]), "=r"(r[2]), "=r"(r[3]) : "r"(addr));
}
__device__ __forceinline__ void cpasync16(uint32_t dst, const void* src) {
    asm volatile("cp.async.cg.shared.global [%0], [%1], 16;" :: "r"(dst), "l"(src));
}
__device__ __forceinline__ void cp_commit() {
    asm volatile("cp.async.commit_group;" ::: "memory");
}
template <int N>
__device__ __forceinline__ void cp_wait() {
    asm volatile("cp.async.wait_group %0;" :: "n"(N) : "memory");
}

__device__ __forceinline__ void split_bf16(float f, __nv_bfloat16& hi, __nv_bfloat16& lo) {
    hi = __float2bfloat16(f);
    lo = __float2bfloat16(f - __bfloat162float(hi));
}

// ---------------------------------------------------------------------------
// RoPE tables
// ---------------------------------------------------------------------------
__global__ void rope_tables_kernel() {
    int idx = blockIdx.x * blockDim.x + threadIdx.x;
    if (idx >= MM * HALF_D) return;
    int m = idx / HALF_D;
    int i = idx % HALF_D;
    double theta_d = pow(10000.0, -2.0 * ((double)i - 1.0) / (double)DD);
    float ang = (float)m * (float)theta_d;
    g_cos[idx] = cosf(ang);
    g_sin[idx] = sinf(ang);
}

// ---------------------------------------------------------------------------
// fp32 -> [hi|lo] split for x
// ---------------------------------------------------------------------------
__global__ void cvt2_x_kernel(const float* __restrict__ src, __nv_bfloat16* __restrict__ dst) {
    long idx = (long)blockIdx.x * blockDim.x + threadIdx.x;
    if (idx >= (long)ROWS * DD) return;
    long row = idx / DD;
    int k = (int)(idx % DD);
    __nv_bfloat16 hi, lo;
    split_bf16(src[idx], hi, lo);
    __nv_bfloat16* r = dst + row * (long)(2 * DD);
    r[k] = hi;
    r[DD + k] = lo;
}

// ---------------------------------------------------------------------------
// All three weights -> [hi|lo] in one launch (z selects w)
// ---------------------------------------------------------------------------
__global__ void cvt2_w_kernel(const float* __restrict__ wq, const float* __restrict__ wk,
                              const float* __restrict__ wv, __nv_bfloat16* __restrict__ dst) {
    long idx = (long)blockIdx.x * blockDim.x + threadIdx.x;
    if (idx >= (long)DD * DD) return;
    const float* src = blockIdx.z == 0 ? wq : (blockIdx.z == 1 ? wk : wv);
    long row = idx / DD;
    int k = (int)(idx % DD);
    __nv_bfloat16 hi, lo;
    split_bf16(src[idx], hi, lo);
    __nv_bfloat16* r = dst + ((long)blockIdx.z * DD + row) * (long)(2 * DD);
    r[k] = hi;
    r[DD + k] = lo;
}

// ---------------------------------------------------------------------------
// V [b*MM + k][n] -> V2T [b*DD + n][hi: k | lo: MM+k]
// ---------------------------------------------------------------------------
__global__ void vT_cvt_kernel(const float* __restrict__ V, __nv_bfloat16* __restrict__ V2T) {
    __shared__ float ts[32][33];
    int b = blockIdx.z;
    int n0 = blockIdx.x * 32, k0 = blockIdx.y * 32;
    int tx = threadIdx.x, ty = threadIdx.y;  // 32 x 8
#pragma unroll
    for (int i = 0; i < 4; i++) {
        int k = k0 + ty + i * 8;
        ts[ty + i * 8][tx] = V[((long)(b * MM + k)) * DD + n0 + tx];
    }
    __syncthreads();
#pragma unroll
    for (int i = 0; i < 4; i++) {
        int n = n0 + ty + i * 8;
        float f = ts[tx][ty + i * 8];
        __nv_bfloat16 hi, lo;
        split_bf16(f, hi, lo);
        __nv_bfloat16* r = V2T + ((long)(b * DD + n)) * (long)(2 * MM);
        int k = k0 + tx;
        r[k] = hi;
        r[MM + k] = lo;
    }
}

// ---------------------------------------------------------------------------
// Row softmax (len MM) fused with [hi|lo] split
// ---------------------------------------------------------------------------
__global__ void __launch_bounds__(256) softmax_cvt_kernel(const float* __restrict__ S,
                                                          __nv_bfloat16* __restrict__ S2) {
    __shared__ float red[256];
    long row = blockIdx.x;
    const float4* p = reinterpret_cast<const float4*>(S + row * (long)MM);
    int t = threadIdx.x;
    float4 v0 = p[t];
    float4 v1 = p[t + 256];

    float mx = fmaxf(fmaxf(fmaxf(v0.x, v0.y), fmaxf(v0.z, v0.w)),
                     fmaxf(fmaxf(v1.x, v1.y), fmaxf(v1.z, v1.w)));
    red[t] = mx;
    __syncthreads();
    for (int s = 128; s > 0; s >>= 1) {
        if (t < s) red[t] = fmaxf(red[t], red[t + s]);
        __syncthreads();
    }
    mx = red[0];
    __syncthreads();

    v0.x = expf(v0.x - mx); v0.y = expf(v0.y - mx);
    v0.z = expf(v0.z - mx); v0.w = expf(v0.w - mx);
    v1.x = expf(v1.x - mx); v1.y = expf(v1.y - mx);
    v1.z = expf(v1.z - mx); v1.w = expf(v1.w - mx);

    float sum = (v0.x + v0.y + v0.z + v0.w) + (v1.x + v1.y + v1.z + v1.w);
    red[t] = sum;
    __syncthreads();
    for (int s = 128; s > 0; s >>= 1) {
        if (t < s) red[t] += red[t + s];
        __syncthreads();
    }
    float inv = 1.0f / red[0];
    __syncthreads();

    __nv_bfloat16* r = S2 + row * (long)(2 * MM);
    float f[8] = {v0.x * inv, v0.y * inv, v0.z * inv, v0.w * inv,
                  v1.x * inv, v1.y * inv, v1.z * inv, v1.w * inv};
    int cb[2] = {4 * t, 1024 + 4 * t};
#pragma unroll
    for (int h = 0; h < 2; h++) {
#pragma unroll
        for (int j = 0; j < 4; j += 2) {
            __nv_bfloat16 h0, l0, h1, l1;
            split_bf16(f[h * 4 + j], h0, l0);
            split_bf16(f[h * 4 + j + 1], h1, l1);
            int k = cb[h] + j;
            *reinterpret_cast<__nv_bfloat162*>(r + k)      = __halves2bfloat162(h0, h1);
            *reinterpret_cast<__nv_bfloat162*>(r + MM + k) = __halves2bfloat162(l0, l1);
        }
    }
}

// ---------------------------------------------------------------------------
// mma.sync bf16 GEMM with virtual 3-segment schedule over [hi|lo] storage.
//   chunk ch: j = ch>>ksh (segment), kk = (ch & (2^ksh -1))*64
//   A offset = kk + (j==1)*K (A pattern [hi,lo,hi])
//   B offset = kk + (j==2)*K (B pattern [hi,hi,lo])
// CTA tile 128 x NTILE, BK=64, 3-stage cp.async, XOR swizzle, 4 warps (2Mx2N).
//   EPI=0: C = alpha * A x B^T (fp32)
//   EPI=1 (NTILE=128 only): merged QKV epilogue with fused RoPE + [hi|lo] split
// ---------------------------------------------------------------------------
template <int EPI, int NTILE>
__global__ void __launch_bounds__(128, NTILE == 64 ? 3 : 2) mma_gemm_kernel(
    const __nv_bfloat16* __restrict__ A, const __nv_bfloat16* __restrict__ B,
    float* __restrict__ C, int Klog, int ksh, int ldc, long sA, long sB, long sC, float alpha)
{
    constexpr int NT = NTILE / 16;            // n8 tiles per warp (8 or 4)
    constexpr int TILE_A = 128 * 64 * 2;      // 16 KB
    constexpr int TILE_B = NTILE * 64 * 2;    // 16 or 8 KB
    constexpr int STAGE = TILE_A + TILE_B;

    extern __shared__ char smem[];
    const uint32_t sb = smem_u32(smem);
    const int tid = threadIdx.x;
    const int wid = tid >> 5, lane = tid & 31;
    const int wm = wid & 1;          // warp M index (x64 rows)
    const int wn = wid >> 1;         // warp N index (x NTILE/2 cols)

    const int lda = 2 * Klog;
    const long row0 = (long)blockIdx.y * 128;
    const long col0 = (long)blockIdx.x * NTILE;
    const __nv_bfloat16* Abase = A + blockIdx.z * sA + row0 * lda;
    const __nv_bfloat16* Bbase = B + blockIdx.z * sB + col0 * lda;
    float* Cbase = C + blockIdx.z * sC;

    const int ldRow = tid >> 3;      // rows 0..15 (+16*i)
    const int ldC = tid & 7;         // 16B chunk within 128B row

    float acc[4][NT][4];
#pragma unroll
    for (int i = 0; i < 4; i++)
#pragma unroll
        for (int j = 0; j < NT; j++)
#pragma unroll
            for (int q = 0; q < 4; q++) acc[i][j][q] = 0.0f;

    const int nch = 3 << ksh;
    const int kmask = (1 << ksh) - 1;

    auto load_tile = [&](int ch, int buf) {
        const int j = ch >> ksh;
        const int kk = (ch & kmask) << 6;
        const long aOff = kk + (j == 1 ? Klog : 0);
        const long bOff = kk + (j == 2 ? Klog : 0);
        const uint32_t sbA = sb + buf * STAGE;
        const uint32_t sbB = sbA + TILE_A;
#pragma unroll
        for (int i = 0; i < 8; i++) {
            int row = ldRow + i * 16;
            uint32_t off = ((uint32_t)row * 8u + (uint32_t)(ldC ^ (row & 7))) * 16u;
            cpasync16(sbA + off, Abase + (long)row * lda + aOff + ldC * 8);
        }
#pragma unroll
        for (int i = 0; i < NTILE / 16; i++) {
            int row = ldRow + i * 16;
            uint32_t off = ((uint32_t)row * 8u + (uint32_t)(ldC ^ (row & 7))) * 16u;
            cpasync16(sbB + off, Bbase + (long)row * lda + bOff + ldC * 8);
        }
    };

    const int lrow = lane & 15;
    const int lcol = lane >> 4;

    load_tile(0, 0);
    cp_commit();
    load_tile(1, 1);
    cp_commit();

    for (int ch = 0; ch < nch; ch++) {
        if (ch + 2 < nch) {
            load_tile(ch + 2, (ch + 2) % 3);
            cp_commit();
            cp_wait<2>();
        } else if (ch + 1 < nch) {
            cp_wait<1>();
        } else {
            cp_wait<0>();
        }
        __syncthreads();

        const uint32_t sbA = sb + (ch % 3) * STAGE;
        const uint32_t sbB = sbA + TILE_A;

        uint32_t fa[2][4][4];
        uint32_t fb[2][NT][2];

        auto load_frags = [&](int ks, int pb) {
#pragma unroll
            for (int mt = 0; mt < 4; mt++) {
                int row = wm * 64 + mt * 16 + lrow;
                int c = 2 * ks + lcol;
                uint32_t addr = sbA + ((uint32_t)row * 8u + (uint32_t)(c ^ (row & 7))) * 16u;
                ldsm4(fa[pb][mt], addr);
            }
#pragma unroll
            for (int p = 0; p < NT / 2; p++) {
                int row = wn * (NTILE / 2) + p * 16 + lrow;
                int c = 2 * ks + lcol;
                uint32_t addr = sbB + ((uint32_t)row * 8u + (uint32_t)(c ^ (row & 7))) * 16u;
                uint32_t r[4];
                ldsm4(r, addr);
                fb[pb][2 * p][0] = r[0]; fb[pb][2 * p][1] = r[2];
                fb[pb][2 * p + 1][0] = r[1]; fb[pb][2 * p + 1][1] = r[3];
            }
        };

        load_frags(0, 0);
#pragma unroll
        for (int ks = 0; ks < 4; ks++) {             // 4 k16 steps in BK=64
            if (ks < 3) load_frags(ks + 1, (ks + 1) & 1);
#pragma unroll
            for (int mt = 0; mt < 4; mt++)
#pragma unroll
                for (int nt = 0; nt < NT; nt++)
                    mma16816(acc[mt][nt], fa[ks & 1][mt], fb[ks & 1][nt]);
        }
        __syncthreads();
    }

    // ---- epilogue ----
    const int g = lane >> 2, tg = lane & 3;
    if (EPI == 0) {
#pragma unroll
        for (int mt = 0; mt < 4; mt++) {
            long r0 = row0 + wm * 64 + mt * 16 + g;
#pragma unroll
            for (int nt = 0; nt < NT; nt++) {
                long cc = col0 + wn * (NTILE / 2) + nt * 8 + tg * 2;
                float2 v0 = make_float2(alpha * acc[mt][nt][0], alpha * acc[mt][nt][1]);
                float2 v1 = make_float2(alpha * acc[mt][nt][2], alpha * acc[mt][nt][3]);
                *reinterpret_cast<float2*>(Cbase + r0 * ldc + cc) = v0;
                *reinterpret_cast<float2*>(Cbase + (r0 + 8) * ldc + cc) = v1;
            }
        }
    } else {
        // merged QKV epilogue. n in [0,3072): Q | K | V
        const int nbase = (int)col0 + wn * (NTILE / 2) + tg * 2;
#pragma unroll
        for (int mt = 0; mt < 4; mt++) {
            long r0 = row0 + wm * 64 + mt * 16 + g;
#pragma unroll
            for (int nt = 0; nt < NT; nt++) {
                int n = nbase + nt * 8;
                if (n < 2048) {
                    int k = n & 1023;
                    int pidx = k >> 1;
#pragma unroll
                    for (int h = 0; h < 2; h++) {
                        long r = r0 + h * 8;
                        int m = (int)(r & (MM - 1));
                        float c = g_cos[(size_t)m * HALF_D + pidx];
                        float s = g_sin[(size_t)m * HALF_D + pidx];
                        float e = acc[mt][nt][2 * h], o = acc[mt][nt][2 * h + 1];
                        float re = e * c + o * s;
                        float ro = -e * s + o * c;
                        __nv_bfloat16 he, le, ho, lo;
                        split_bf16(re, he, le);
                        split_bf16(ro, ho, lo);
                        __nv_bfloat16* dst = (n < 1024 ? g_Q2 : g_K2) + r * (long)(2 * DD) + k;
                        *reinterpret_cast<__nv_bfloat162*>(dst)      = __halves2bfloat162(he, ho);
                        *reinterpret_cast<__nv_bfloat162*>(dst + DD) = __halves2bfloat162(le, lo);
                    }
                } else {
                    int k = n - 2048;
                    float2 v0 = make_float2(acc[mt][nt][0], acc[mt][nt][1]);
                    float2 v1 = make_float2(acc[mt][nt][2], acc[mt][nt][3]);
                    *reinterpret_cast<float2*>(g_Vf + r0 * DD + k) = v0;
                    *reinterpret_cast<float2*>(g_Vf + (r0 + 8) * DD + k) = v1;
                }
            }
        }
    }
}

// ---------------------------------------------------------------------------
// Launch.  Scores GEMM kept at launch index 5 for the ncu capture.
// ---------------------------------------------------------------------------
extern "C" void kernel_launch(void* const* d_in, const int* in_sizes, int n_in,
                              void* d_out, int out_size) {
    (void)in_sizes; (void)n_in; (void)out_size;
    const float* x  = (const float*)d_in[0];
    const float* wq = (const float*)d_in[1];
    const float* wk = (const float*)d_in[2];
    const float* wv = (const float*)d_in[3];
    float* out = (float*)d_out;

    __nv_bfloat16 *x2, *w2, *Q2, *K2, *V2T, *S2;
    float *Vf, *Sf;
    cudaGetSymbolAddress((void**)&x2, g_x2);
    cudaGetSymbolAddress((void**)&w2, g_w2);
    cudaGetSymbolAddress((void**)&Vf, g_Vf);
    cudaGetSymbolAddress((void**)&Q2, g_Q2);
    cudaGetSymbolAddress((void**)&K2, g_K2);
    cudaGetSymbolAddress((void**)&V2T, g_V2T);
    cudaGetSymbolAddress((void**)&Sf, g_Sf);
    cudaGetSymbolAddress((void**)&S2, g_S2);

    constexpr int SMEM128 = 3 * (128 * 64 * 2 + 128 * 64 * 2);   // 96 KB
    constexpr int SMEM64  = 3 * (128 * 64 * 2 + 64 * 64 * 2);    // 72 KB
    cudaFuncSetAttribute(mma_gemm_kernel<0, 128>, cudaFuncAttributeMaxDynamicSharedMemorySize, SMEM128);
    cudaFuncSetAttribute(mma_gemm_kernel<1, 128>, cudaFuncAttributeMaxDynamicSharedMemorySize, SMEM128);
    cudaFuncSetAttribute(mma_gemm_kernel<0, 64>,  cudaFuncAttributeMaxDynamicSharedMemorySize, SMEM64);

    // 0: RoPE tables
    rope_tables_kernel<<<(MM * HALF_D + 255) / 256, 256>>>();
    // 1: x -> [hi|lo]
    cvt2_x_kernel<<<(int)(((long)ROWS * DD + 255) / 256), 256>>>(x, x2);
    // 2: weights -> [hi|lo]
    dim3 gW((DD * DD + 255) / 256, 1, 3);
    cvt2_w_kernel<<<gW, 256>>>(wq, wk, wv, w2);

    // 3: Merged QKV projection with fused RoPE/split epilogue (Klog=1024, ksh=4)
    dim3 gProj(3 * DD / 128, ROWS / 128, 1);
    mma_gemm_kernel<1, 128><<<gProj, 128, SMEM128>>>(x2, w2, nullptr, DD, 4, 0, 0, 0, 0, 1.0f);

    // 4: V transpose + split
    dim3 gV(DD / 32, MM / 32, BB);
    vT_cvt_kernel<<<gV, dim3(32, 8)>>>(Vf, V2T);

    // 5: scores = Qr @ Kr^T / 32   <- ncu capture target (Klog=1024, ksh=4)
    dim3 gScore(MM / 128, MM / 128, BB);
    mma_gemm_kernel<0, 128><<<gScore, 128, SMEM128>>>(Q2, K2, Sf, DD, 4, MM,
                                                      (long)MM * 2 * DD, (long)MM * 2 * DD,
                                                      (long)MM * MM, 0.03125f);

    // 6: softmax + split
    softmax_cvt_kernel<<<BB * MM, 256>>>(Sf, S2);

    // 7: out = attn @ V  (Klog=2048, ksh=5, 128x64 tiles for tail reduction)
    dim3 gOut(DD / 64, MM / 128, BB);
    mma_gemm_kernel<0, 64><<<gOut, 128, SMEM64>>>(S2, V2T, out, MM, 5, DD,
                                                  (long)MM * 2 * MM, (long)DD * 2 * MM,
                                                  (long)MM * DD, 1.0f);
}

// round 8
// speedup vs baseline: 1.3705x; 1.3705x over previous
#include <cuda_runtime.h>
#include <cuda_fp16.h>
#include <math.h>
#include <stdint.h>

// Problem dims (fixed)
#define BB 8
#define MM 2048
#define DD 1024
#define HALF_D 512
#define ROWS 16384           // BB*MM

// ---------------------------------------------------------------------------
// Device-global scratch. 2-segment fp16 storage [hi | lo], each K wide.
// GEMM schedule: A:[ah, al] x B:[bh, bh]  (term ah*bl ~2^-11 dropped)
// ---------------------------------------------------------------------------
__device__ __half g_x2[(size_t)ROWS * 2 * DD];      // x  [hi|lo]
__device__ __half g_w2[(size_t)(3 * DD) * 2 * DD];  // [wq;wk;wv] [hi|lo]
__device__ float g_Vf[(size_t)ROWS * DD];
__device__ __half g_Q2[(size_t)ROWS * 2 * DD];      // rotated Q [hi|lo]
__device__ __half g_K2[(size_t)ROWS * 2 * DD];      // rotated K [hi|lo]
__device__ __half g_V2T[(size_t)BB * DD * 2 * MM];  // V^T [hi|lo]
__device__ float g_Sf[(size_t)BB * MM * MM];        // scores fp32
__device__ __half g_S2[(size_t)BB * MM * 2 * MM];   // attn [hi|lo]
__device__ float g_cos[(size_t)MM * HALF_D];
__device__ float g_sin[(size_t)MM * HALF_D];

// ---------------------------------------------------------------------------
// PTX helpers (base-ISA: mma.sync / ldmatrix / cp.async)
// ---------------------------------------------------------------------------
__device__ __forceinline__ uint32_t smem_u32(const void* p) {
    uint32_t a;
    asm("{ .reg .u64 t; cvta.to.shared.u64 t, %1; cvt.u32.u64 %0, t; }" : "=r"(a) : "l"(p));
    return a;
}
__device__ __forceinline__ void mma16816(float* d, const uint32_t* a, const uint32_t* b) {
    asm volatile(
        "mma.sync.aligned.m16n8k16.row.col.f32.f16.f16.f32 "
        "{%0,%1,%2,%3}, {%4,%5,%6,%7}, {%8,%9}, {%0,%1,%2,%3};"
        : "+f"(d[0]), "+f"(d[1]), "+f"(d[2]), "+f"(d[3])
        : "r"(a[0]), "r"(a[1]), "r"(a[2]), "r"(a[3]), "r"(b[0]), "r"(b[1]));
}
__device__ __forceinline__ void ldsm4(uint32_t* r, uint32_t addr) {
    asm volatile("ldmatrix.sync.aligned.m8n8.x4.shared.b16 {%0,%1,%2,%3}, [%4];"
                 : "=r"(r[0]), "=r"(r[1]), "=r"(r[2]), "=r"(r[3]) : "r"(addr));
}
__device__ __forceinline__ void cpasync16(uint32_t dst, const void* src) {
    asm volatile("cp.async.cg.shared.global [%0], [%1], 16;" :: "r"(dst), "l"(src));
}
__device__ __forceinline__ void cp_commit() {
    asm volatile("cp.async.commit_group;" ::: "memory");
}
template <int N>
__device__ __forceinline__ void cp_wait() {
    asm volatile("cp.async.wait_group %0;" :: "n"(N) : "memory");
}

__device__ __forceinline__ void split_f16(float f, __half& hi, __half& lo) {
    hi = __float2half(f);
    lo = __float2half(f - __half2float(hi));
}

// ---------------------------------------------------------------------------
// RoPE tables
// ---------------------------------------------------------------------------
__global__ void rope_tables_kernel() {
    int idx = blockIdx.x * blockDim.x + threadIdx.x;
    if (idx >= MM * HALF_D) return;
    int m = idx / HALF_D;
    int i = idx % HALF_D;
    double theta_d = pow(10000.0, -2.0 * ((double)i - 1.0) / (double)DD);
    float ang = (float)m * (float)theta_d;
    g_cos[idx] = cosf(ang);
    g_sin[idx] = sinf(ang);
}

// ---------------------------------------------------------------------------
// fp32 -> [hi|lo] fp16 split for x
// ---------------------------------------------------------------------------
__global__ void cvt2_x_kernel(const float* __restrict__ src, __half* __restrict__ dst) {
    long idx = (long)blockIdx.x * blockDim.x + threadIdx.x;
    if (idx >= (long)ROWS * DD) return;
    long row = idx / DD;
    int k = (int)(idx % DD);
    __half hi, lo;
    split_f16(src[idx], hi, lo);
    __half* r = dst + row * (long)(2 * DD);
    r[k] = hi;
    r[DD + k] = lo;
}

// ---------------------------------------------------------------------------
// All three weights -> [hi|lo] in one launch (z selects w)
// ---------------------------------------------------------------------------
__global__ void cvt2_w_kernel(const float* __restrict__ wq, const float* __restrict__ wk,
                              const float* __restrict__ wv, __half* __restrict__ dst) {
    long idx = (long)blockIdx.x * blockDim.x + threadIdx.x;
    if (idx >= (long)DD * DD) return;
    const float* src = blockIdx.z == 0 ? wq : (blockIdx.z == 1 ? wk : wv);
    long row = idx / DD;
    int k = (int)(idx % DD);
    __half hi, lo;
    split_f16(src[idx], hi, lo);
    __half* r = dst + ((long)blockIdx.z * DD + row) * (long)(2 * DD);
    r[k] = hi;
    r[DD + k] = lo;
}

// ---------------------------------------------------------------------------
// V [b*MM + k][n] -> V2T [b*DD + n][hi: k | lo: MM+k]
// ---------------------------------------------------------------------------
__global__ void vT_cvt_kernel(const float* __restrict__ V, __half* __restrict__ V2T) {
    __shared__ float ts[32][33];
    int b = blockIdx.z;
    int n0 = blockIdx.x * 32, k0 = blockIdx.y * 32;
    int tx = threadIdx.x, ty = threadIdx.y;  // 32 x 8
#pragma unroll
    for (int i = 0; i < 4; i++) {
        int k = k0 + ty + i * 8;
        ts[ty + i * 8][tx] = V[((long)(b * MM + k)) * DD + n0 + tx];
    }
    __syncthreads();
#pragma unroll
    for (int i = 0; i < 4; i++) {
        int n = n0 + ty + i * 8;
        float f = ts[tx][ty + i * 8];
        __half hi, lo;
        split_f16(f, hi, lo);
        __half* r = V2T + ((long)(b * DD + n)) * (long)(2 * MM);
        int k = k0 + tx;
        r[k] = hi;
        r[MM + k] = lo;
    }
}

// ---------------------------------------------------------------------------
// Row softmax (len MM) fused with [hi|lo] fp16 split
// ---------------------------------------------------------------------------
__global__ void __launch_bounds__(256) softmax_cvt_kernel(const float* __restrict__ S,
                                                          __half* __restrict__ S2) {
    __shared__ float red[256];
    long row = blockIdx.x;
    const float4* p = reinterpret_cast<const float4*>(S + row * (long)MM);
    int t = threadIdx.x;
    float4 v0 = p[t];
    float4 v1 = p[t + 256];

    float mx = fmaxf(fmaxf(fmaxf(v0.x, v0.y), fmaxf(v0.z, v0.w)),
                     fmaxf(fmaxf(v1.x, v1.y), fmaxf(v1.z, v1.w)));
    red[t] = mx;
    __syncthreads();
    for (int s = 128; s > 0; s >>= 1) {
        if (t < s) red[t] = fmaxf(red[t], red[t + s]);
        __syncthreads();
    }
    mx = red[0];
    __syncthreads();

    v0.x = expf(v0.x - mx); v0.y = expf(v0.y - mx);
    v0.z = expf(v0.z - mx); v0.w = expf(v0.w - mx);
    v1.x = expf(v1.x - mx); v1.y = expf(v1.y - mx);
    v1.z = expf(v1.z - mx); v1.w = expf(v1.w - mx);

    float sum = (v0.x + v0.y + v0.z + v0.w) + (v1.x + v1.y + v1.z + v1.w);
    red[t] = sum;
    __syncthreads();
    for (int s = 128; s > 0; s >>= 1) {
        if (t < s) red[t] += red[t + s];
        __syncthreads();
    }
    float inv = 1.0f / red[0];
    __syncthreads();

    __half* r = S2 + row * (long)(2 * MM);
    float f[8] = {v0.x * inv, v0.y * inv, v0.z * inv, v0.w * inv,
                  v1.x * inv, v1.y * inv, v1.z * inv, v1.w * inv};
    int cb[2] = {4 * t, 1024 + 4 * t};
#pragma unroll
    for (int h = 0; h < 2; h++) {
#pragma unroll
        for (int j = 0; j < 4; j += 2) {
            __half h0, l0, h1, l1;
            split_f16(f[h * 4 + j], h0, l0);
            split_f16(f[h * 4 + j + 1], h1, l1);
            int k = cb[h] + j;
            *reinterpret_cast<__half2*>(r + k)      = __halves2half2(h0, h1);
            *reinterpret_cast<__half2*>(r + MM + k) = __halves2half2(l0, l1);
        }
    }
}

// ---------------------------------------------------------------------------
// mma.sync fp16 GEMM, virtual 2-segment schedule over [hi|lo] storage.
//   chunk ch: j = ch>>ksh (segment 0=hi,1=lo), kk = (ch & (2^ksh-1))*64
//   A offset = kk + j*K   (A: [ah, al])
//   B offset = kk         (B: [bh, bh])
// CTA tile 128 x NTILE, BK=64, 3-stage cp.async, XOR swizzle, 4 warps (2Mx2N),
// register fragment double-buffering.
//   EPI=0: C = alpha * A x B^T (fp32)
//   EPI=1 (NTILE=128): merged QKV epilogue with fused RoPE + [hi|lo] split
// ---------------------------------------------------------------------------
template <int EPI, int NTILE>
__global__ void __launch_bounds__(128, NTILE == 64 ? 3 : 2) mma_gemm_kernel(
    const __half* __restrict__ A, const __half* __restrict__ B,
    float* __restrict__ C, int Klog, int ksh, int ldc, long sA, long sB, long sC, float alpha)
{
    constexpr int NT = NTILE / 16;            // n8 tiles per warp (8 or 4)
    constexpr int TILE_A = 128 * 64 * 2;      // 16 KB
    constexpr int TILE_B = NTILE * 64 * 2;    // 16 or 8 KB
    constexpr int STAGE = TILE_A + TILE_B;

    extern __shared__ char smem[];
    const uint32_t sb = smem_u32(smem);
    const int tid = threadIdx.x;
    const int wid = tid >> 5, lane = tid & 31;
    const int wm = wid & 1;          // warp M index (x64 rows)
    const int wn = wid >> 1;         // warp N index (x NTILE/2 cols)

    const int lda = 2 * Klog;
    const long row0 = (long)blockIdx.y * 128;
    const long col0 = (long)blockIdx.x * NTILE;
    const __half* Abase = A + blockIdx.z * sA + row0 * lda;
    const __half* Bbase = B + blockIdx.z * sB + col0 * lda;
    float* Cbase = C + blockIdx.z * sC;

    const int ldRow = tid >> 3;      // rows 0..15 (+16*i)
    const int ldC = tid & 7;         // 16B chunk within 128B row

    float acc[4][NT][4];
#pragma unroll
    for (int i = 0; i < 4; i++)
#pragma unroll
        for (int j = 0; j < NT; j++)
#pragma unroll
            for (int q = 0; q < 4; q++) acc[i][j][q] = 0.0f;

    const int nch = 2 << ksh;
    const int kmask = (1 << ksh) - 1;

    auto load_tile = [&](int ch, int buf) {
        const int j = ch >> ksh;
        const int kk = (ch & kmask) << 6;
        const long aOff = kk + (j == 1 ? Klog : 0);
        const long bOff = kk;
        const uint32_t sbA = sb + buf * STAGE;
        const uint32_t sbB = sbA + TILE_A;
#pragma unroll
        for (int i = 0; i < 8; i++) {
            int row = ldRow + i * 16;
            uint32_t off = ((uint32_t)row * 8u + (uint32_t)(ldC ^ (row & 7))) * 16u;
            cpasync16(sbA + off, Abase + (long)row * lda + aOff + ldC * 8);
        }
#pragma unroll
        for (int i = 0; i < NTILE / 16; i++) {
            int row = ldRow + i * 16;
            uint32_t off = ((uint32_t)row * 8u + (uint32_t)(ldC ^ (row & 7))) * 16u;
            cpasync16(sbB + off, Bbase + (long)row * lda + bOff + ldC * 8);
        }
    };

    const int lrow = lane & 15;
    const int lcol = lane >> 4;

    load_tile(0, 0);
    cp_commit();
    load_tile(1, 1);
    cp_commit();

    for (int ch = 0; ch < nch; ch++) {
        if (ch + 2 < nch) {
            load_tile(ch + 2, (ch + 2) % 3);
            cp_commit();
            cp_wait<2>();
        } else if (ch + 1 < nch) {
            cp_wait<1>();
        } else {
            cp_wait<0>();
        }
        __syncthreads();

        const uint32_t sbA = sb + (ch % 3) * STAGE;
        const uint32_t sbB = sbA + TILE_A;

        uint32_t fa[2][4][4];
        uint32_t fb[2][NT][2];

        auto load_frags = [&](int ks, int pb) {
#pragma unroll
            for (int mt = 0; mt < 4; mt++) {
                int row = wm * 64 + mt * 16 + lrow;
                int c = 2 * ks + lcol;
                uint32_t addr = sbA + ((uint32_t)row * 8u + (uint32_t)(c ^ (row & 7))) * 16u;
                ldsm4(fa[pb][mt], addr);
            }
#pragma unroll
            for (int p = 0; p < NT / 2; p++) {
                int row = wn * (NTILE / 2) + p * 16 + lrow;
                int c = 2 * ks + lcol;
                uint32_t addr = sbB + ((uint32_t)row * 8u + (uint32_t)(c ^ (row & 7))) * 16u;
                uint32_t r[4];
                ldsm4(r, addr);
                fb[pb][2 * p][0] = r[0]; fb[pb][2 * p][1] = r[2];
                fb[pb][2 * p + 1][0] = r[1]; fb[pb][2 * p + 1][1] = r[3];
            }
        };

        load_frags(0, 0);
#pragma unroll
        for (int ks = 0; ks < 4; ks++) {             // 4 k16 steps in BK=64
            if (ks < 3) load_frags(ks + 1, (ks + 1) & 1);
#pragma unroll
            for (int mt = 0; mt < 4; mt++)
#pragma unroll
                for (int nt = 0; nt < NT; nt++)
                    mma16816(acc[mt][nt], fa[ks & 1][mt], fb[ks & 1][nt]);
        }
        __syncthreads();
    }

    // ---- epilogue ----
    const int g = lane >> 2, tg = lane & 3;
    if (EPI == 0) {
#pragma unroll
        for (int mt = 0; mt < 4; mt++) {
            long r0 = row0 + wm * 64 + mt * 16 + g;
#pragma unroll
            for (int nt = 0; nt < NT; nt++) {
                long cc = col0 + wn * (NTILE / 2) + nt * 8 + tg * 2;
                float2 v0 = make_float2(alpha * acc[mt][nt][0], alpha * acc[mt][nt][1]);
                float2 v1 = make_float2(alpha * acc[mt][nt][2], alpha * acc[mt][nt][3]);
                *reinterpret_cast<float2*>(Cbase + r0 * ldc + cc) = v0;
                *reinterpret_cast<float2*>(Cbase + (r0 + 8) * ldc + cc) = v1;
            }
        }
    } else {
        // merged QKV epilogue. n in [0,3072): Q | K | V
        const int nbase = (int)col0 + wn * (NTILE / 2) + tg * 2;
#pragma unroll
        for (int mt = 0; mt < 4; mt++) {
            long r0 = row0 + wm * 64 + mt * 16 + g;
#pragma unroll
            for (int nt = 0; nt < NT; nt++) {
                int n = nbase + nt * 8;
                if (n < 2048) {
                    int k = n & 1023;
                    int pidx = k >> 1;
#pragma unroll
                    for (int h = 0; h < 2; h++) {
                        long r = r0 + h * 8;
                        int m = (int)(r & (MM - 1));
                        float c = g_cos[(size_t)m * HALF_D + pidx];
                        float s = g_sin[(size_t)m * HALF_D + pidx];
                        float e = acc[mt][nt][2 * h], o = acc[mt][nt][2 * h + 1];
                        float re = e * c + o * s;
                        float ro = -e * s + o * c;
                        __half he, le, ho, lo;
                        split_f16(re, he, le);
                        split_f16(ro, ho, lo);
                        __half* dst = (n < 1024 ? g_Q2 : g_K2) + r * (long)(2 * DD) + k;
                        *reinterpret_cast<__half2*>(dst)      = __halves2half2(he, ho);
                        *reinterpret_cast<__half2*>(dst + DD) = __halves2half2(le, lo);
                    }
                } else {
                    int k = n - 2048;
                    float2 v0 = make_float2(acc[mt][nt][0], acc[mt][nt][1]);
                    float2 v1 = make_float2(acc[mt][nt][2], acc[mt][nt][3]);
                    *reinterpret_cast<float2*>(g_Vf + r0 * DD + k) = v0;
                    *reinterpret_cast<float2*>(g_Vf + (r0 + 8) * DD + k) = v1;
                }
            }
        }
    }
}

// ---------------------------------------------------------------------------
// Launch.  Scores GEMM kept at launch index 5 for the ncu capture.
// ---------------------------------------------------------------------------
extern "C" void kernel_launch(void* const* d_in, const int* in_sizes, int n_in,
                              void* d_out, int out_size) {
    (void)in_sizes; (void)n_in; (void)out_size;
    const float* x  = (const float*)d_in[0];
    const float* wq = (const float*)d_in[1];
    const float* wk = (const float*)d_in[2];
    const float* wv = (const float*)d_in[3];
    float* out = (float*)d_out;

    __half *x2, *w2, *Q2, *K2, *V2T, *S2;
    float *Vf, *Sf;
    cudaGetSymbolAddress((void**)&x2, g_x2);
    cudaGetSymbolAddress((void**)&w2, g_w2);
    cudaGetSymbolAddress((void**)&Vf, g_Vf);
    cudaGetSymbolAddress((void**)&Q2, g_Q2);
    cudaGetSymbolAddress((void**)&K2, g_K2);
    cudaGetSymbolAddress((void**)&V2T, g_V2T);
    cudaGetSymbolAddress((void**)&Sf, g_Sf);
    cudaGetSymbolAddress((void**)&S2, g_S2);

    constexpr int SMEM128 = 3 * (128 * 64 * 2 + 128 * 64 * 2);   // 96 KB
    constexpr int SMEM64  = 3 * (128 * 64 * 2 + 64 * 64 * 2);    // 72 KB
    cudaFuncSetAttribute(mma_gemm_kernel<0, 128>, cudaFuncAttributeMaxDynamicSharedMemorySize, SMEM128);
    cudaFuncSetAttribute(mma_gemm_kernel<1, 128>, cudaFuncAttributeMaxDynamicSharedMemorySize, SMEM128);
    cudaFuncSetAttribute(mma_gemm_kernel<0, 64>,  cudaFuncAttributeMaxDynamicSharedMemorySize, SMEM64);

    // 0: RoPE tables
    rope_tables_kernel<<<(MM * HALF_D + 255) / 256, 256>>>();
    // 1: x -> [hi|lo]
    cvt2_x_kernel<<<(int)(((long)ROWS * DD + 255) / 256), 256>>>(x, x2);
    // 2: weights -> [hi|lo]
    dim3 gW((DD * DD + 255) / 256, 1, 3);
    cvt2_w_kernel<<<gW, 256>>>(wq, wk, wv, w2);

    // 3: Merged QKV projection with fused RoPE/split epilogue (Klog=1024, ksh=4)
    dim3 gProj(3 * DD / 128, ROWS / 128, 1);
    mma_gemm_kernel<1, 128><<<gProj, 128, SMEM128>>>(x2, w2, nullptr, DD, 4, 0, 0, 0, 0, 1.0f);

    // 4: V transpose + split
    dim3 gV(DD / 32, MM / 32, BB);
    vT_cvt_kernel<<<gV, dim3(32, 8)>>>(Vf, V2T);

    // 5: scores = Qr @ Kr^T / 32   <- ncu capture target (Klog=1024, ksh=4)
    dim3 gScore(MM / 128, MM / 128, BB);
    mma_gemm_kernel<0, 128><<<gScore, 128, SMEM128>>>(Q2, K2, Sf, DD, 4, MM,
                                                      (long)MM * 2 * DD, (long)MM * 2 * DD,
                                                      (long)MM * MM, 0.03125f);

    // 6: softmax + split
    softmax_cvt_kernel<<<BB * MM, 256>>>(Sf, S2);

    // 7: out = attn @ V  (Klog=2048, ksh=5, 128x64 tiles)
    dim3 gOut(DD / 64, MM / 128, BB);
    mma_gemm_kernel<0, 64><<<gOut, 128, SMEM64>>>(S2, V2T, out, MM, 5, DD,
                                                  (long)MM * 2 * MM, (long)DD * 2 * MM,
                                                  (long)MM * DD, 1.0f);
}

// round 9
// speedup vs baseline: 2.2941x; 1.6739x over previous
#include <cuda_runtime.h>
#include <cuda_fp16.h>
#include <math.h>
#include <stdint.h>

// Problem dims (fixed)
#define BB 8
#define MM 2048
#define DD 1024
#define HALF_D 512
#define ROWS 16384           // BB*MM

// ---------------------------------------------------------------------------
// Device-global scratch (allocation-free, graph-capture safe). Plain fp16.
// ---------------------------------------------------------------------------
__device__ __half g_xh[(size_t)ROWS * DD];        // x fp16
__device__ __half g_wh[(size_t)(3 * DD) * DD];    // [wq;wk;wv] fp16
__device__ float g_Vf[(size_t)ROWS * DD];
__device__ __half g_Qh[(size_t)ROWS * DD];        // rotated Q fp16
__device__ __half g_Kh[(size_t)ROWS * DD];        // rotated K fp16
__device__ __half g_VhT[(size_t)BB * DD * MM];    // V^T fp16
__device__ float g_Sf[(size_t)BB * MM * MM];      // scores fp32
__device__ __half g_Sh[(size_t)BB * MM * MM];     // attn fp16
__device__ float g_cos[(size_t)MM * HALF_D];
__device__ float g_sin[(size_t)MM * HALF_D];

// ---------------------------------------------------------------------------
// PTX helpers (base-ISA: mma.sync / ldmatrix / cp.async)
// ---------------------------------------------------------------------------
__device__ __forceinline__ uint32_t smem_u32(const void* p) {
    uint32_t a;
    asm("{ .reg .u64 t; cvta.to.shared.u64 t, %1; cvt.u32.u64 %0, t; }" : "=r"(a) : "l"(p));
    return a;
}
__device__ __forceinline__ void mma16816(float* d, const uint32_t* a, const uint32_t* b) {
    asm volatile(
        "mma.sync.aligned.m16n8k16.row.col.f32.f16.f16.f32 "
        "{%0,%1,%2,%3}, {%4,%5,%6,%7}, {%8,%9}, {%0,%1,%2,%3};"
        : "+f"(d[0]), "+f"(d[1]), "+f"(d[2]), "+f"(d[3])
        : "r"(a[0]), "r"(a[1]), "r"(a[2]), "r"(a[3]), "r"(b[0]), "r"(b[1]));
}
__device__ __forceinline__ void ldsm4(uint32_t* r, uint32_t addr) {
    asm volatile("ldmatrix.sync.aligned.m8n8.x4.shared.b16 {%0,%1,%2,%3}, [%4];"
                 : "=r"(r[0]), "=r"(r[1]), "=r"(r[2]), "=r"(r[3]) : "r"(addr));
}
__device__ __forceinline__ void cpasync16(uint32_t dst, const void* src) {
    asm volatile("cp.async.cg.shared.global [%0], [%1], 16;" :: "r"(dst), "l"(src));
}
__device__ __forceinline__ void cp_commit() {
    asm volatile("cp.async.commit_group;" ::: "memory");
}
template <int N>
__device__ __forceinline__ void cp_wait() {
    asm volatile("cp.async.wait_group %0;" :: "n"(N) : "memory");
}

// ---------------------------------------------------------------------------
// RoPE tables
// ---------------------------------------------------------------------------
__global__ void rope_tables_kernel() {
    int idx = blockIdx.x * blockDim.x + threadIdx.x;
    if (idx >= MM * HALF_D) return;
    int m = idx / HALF_D;
    int i = idx % HALF_D;
    double theta_d = pow(10000.0, -2.0 * ((double)i - 1.0) / (double)DD);
    float ang = (float)m * (float)theta_d;
    g_cos[idx] = cosf(ang);
    g_sin[idx] = sinf(ang);
}

// ---------------------------------------------------------------------------
// fp32 -> fp16 for x
// ---------------------------------------------------------------------------
__global__ void cvt_x_kernel(const float* __restrict__ src, __half* __restrict__ dst) {
    long idx = ((long)blockIdx.x * blockDim.x + threadIdx.x) * 4;
    if (idx >= (long)ROWS * DD) return;
    float4 v = *reinterpret_cast<const float4*>(src + idx);
    __half2 a = __floats2half2_rn(v.x, v.y);
    __half2 b = __floats2half2_rn(v.z, v.w);
    *reinterpret_cast<__half2*>(dst + idx) = a;
    *reinterpret_cast<__half2*>(dst + idx + 2) = b;
}

// ---------------------------------------------------------------------------
// All three weights -> fp16 in one launch (z selects w)
// ---------------------------------------------------------------------------
__global__ void cvt_w_kernel(const float* __restrict__ wq, const float* __restrict__ wk,
                             const float* __restrict__ wv, __half* __restrict__ dst) {
    long idx = ((long)blockIdx.x * blockDim.x + threadIdx.x) * 4;
    if (idx >= (long)DD * DD) return;
    const float* src = blockIdx.z == 0 ? wq : (blockIdx.z == 1 ? wk : wv);
    float4 v = *reinterpret_cast<const float4*>(src + idx);
    __half* r = dst + (long)blockIdx.z * DD * DD + idx;
    *reinterpret_cast<__half2*>(r)     = __floats2half2_rn(v.x, v.y);
    *reinterpret_cast<__half2*>(r + 2) = __floats2half2_rn(v.z, v.w);
}

// ---------------------------------------------------------------------------
// V [b*MM + k][n] -> VhT [b*DD + n][k]  fp16 transpose
// ---------------------------------------------------------------------------
__global__ void vT_cvt_kernel(const float* __restrict__ V, __half* __restrict__ VhT) {
    __shared__ float ts[32][33];
    int b = blockIdx.z;
    int n0 = blockIdx.x * 32, k0 = blockIdx.y * 32;
    int tx = threadIdx.x, ty = threadIdx.y;  // 32 x 8
#pragma unroll
    for (int i = 0; i < 4; i++) {
        int k = k0 + ty + i * 8;
        ts[ty + i * 8][tx] = V[((long)(b * MM + k)) * DD + n0 + tx];
    }
    __syncthreads();
#pragma unroll
    for (int i = 0; i < 4; i++) {
        int n = n0 + ty + i * 8;
        VhT[((long)(b * DD + n)) * MM + k0 + tx] = __float2half(ts[tx][ty + i * 8]);
    }
}

// ---------------------------------------------------------------------------
// Row softmax (len MM) fused with fp16 conversion
// ---------------------------------------------------------------------------
__global__ void __launch_bounds__(256) softmax_cvt_kernel(const float* __restrict__ S,
                                                          __half* __restrict__ Sh) {
    __shared__ float red[256];
    long row = blockIdx.x;
    const float4* p = reinterpret_cast<const float4*>(S + row * (long)MM);
    int t = threadIdx.x;
    float4 v0 = p[t];
    float4 v1 = p[t + 256];

    float mx = fmaxf(fmaxf(fmaxf(v0.x, v0.y), fmaxf(v0.z, v0.w)),
                     fmaxf(fmaxf(v1.x, v1.y), fmaxf(v1.z, v1.w)));
    red[t] = mx;
    __syncthreads();
    for (int s = 128; s > 0; s >>= 1) {
        if (t < s) red[t] = fmaxf(red[t], red[t + s]);
        __syncthreads();
    }
    mx = red[0];
    __syncthreads();

    v0.x = expf(v0.x - mx); v0.y = expf(v0.y - mx);
    v0.z = expf(v0.z - mx); v0.w = expf(v0.w - mx);
    v1.x = expf(v1.x - mx); v1.y = expf(v1.y - mx);
    v1.z = expf(v1.z - mx); v1.w = expf(v1.w - mx);

    float sum = (v0.x + v0.y + v0.z + v0.w) + (v1.x + v1.y + v1.z + v1.w);
    red[t] = sum;
    __syncthreads();
    for (int s = 128; s > 0; s >>= 1) {
        if (t < s) red[t] += red[t + s];
        __syncthreads();
    }
    float inv = 1.0f / red[0];
    __syncthreads();

    __half* r = Sh + row * (long)MM;
    *reinterpret_cast<__half2*>(r + 4 * t)            = __floats2half2_rn(v0.x * inv, v0.y * inv);
    *reinterpret_cast<__half2*>(r + 4 * t + 2)        = __floats2half2_rn(v0.z * inv, v0.w * inv);
    *reinterpret_cast<__half2*>(r + 1024 + 4 * t)     = __floats2half2_rn(v1.x * inv, v1.y * inv);
    *reinterpret_cast<__half2*>(r + 1024 + 4 * t + 2) = __floats2half2_rn(v1.z * inv, v1.w * inv);
}

// ---------------------------------------------------------------------------
// mma.sync fp16 GEMM (NT, both operands K-major).
// CTA tile 128 x NTILE, BK=64, 3-stage cp.async, XOR swizzle, 4 warps (2Mx2N),
// register fragment double-buffering.
//   EPI=0: C = alpha * A x B^T (fp32)
//   EPI=1 (NTILE=128): merged QKV epilogue with fused RoPE, fp16 out
// ---------------------------------------------------------------------------
template <int EPI, int NTILE>
__global__ void __launch_bounds__(128, NTILE == 64 ? 3 : 2) mma_gemm_kernel(
    const __half* __restrict__ A, const __half* __restrict__ B,
    float* __restrict__ C, int K, int ldc, long sA, long sB, long sC, float alpha)
{
    constexpr int NT = NTILE / 16;            // n8 tiles per warp (8 or 4)
    constexpr int TILE_A = 128 * 64 * 2;      // 16 KB
    constexpr int TILE_B = NTILE * 64 * 2;    // 16 or 8 KB
    constexpr int STAGE = TILE_A + TILE_B;

    extern __shared__ char smem[];
    const uint32_t sb = smem_u32(smem);
    const int tid = threadIdx.x;
    const int wid = tid >> 5, lane = tid & 31;
    const int wm = wid & 1;          // warp M index (x64 rows)
    const int wn = wid >> 1;         // warp N index (x NTILE/2 cols)

    const long row0 = (long)blockIdx.y * 128;
    const long col0 = (long)blockIdx.x * NTILE;
    const __half* Abase = A + blockIdx.z * sA + row0 * K;
    const __half* Bbase = B + blockIdx.z * sB + col0 * K;
    float* Cbase = C + blockIdx.z * sC;

    const int ldRow = tid >> 3;      // rows 0..15 (+16*i)
    const int ldC = tid & 7;         // 16B chunk within 128B row

    float acc[4][NT][4];
#pragma unroll
    for (int i = 0; i < 4; i++)
#pragma unroll
        for (int j = 0; j < NT; j++)
#pragma unroll
            for (int q = 0; q < 4; q++) acc[i][j][q] = 0.0f;

    const int nch = K >> 6;

    auto load_tile = [&](int ch, int buf) {
        const int kk = ch << 6;
        const uint32_t sbA = sb + buf * STAGE;
        const uint32_t sbB = sbA + TILE_A;
#pragma unroll
        for (int i = 0; i < 8; i++) {
            int row = ldRow + i * 16;
            uint32_t off = ((uint32_t)row * 8u + (uint32_t)(ldC ^ (row & 7))) * 16u;
            cpasync16(sbA + off, Abase + (long)row * K + kk + ldC * 8);
        }
#pragma unroll
        for (int i = 0; i < NTILE / 16; i++) {
            int row = ldRow + i * 16;
            uint32_t off = ((uint32_t)row * 8u + (uint32_t)(ldC ^ (row & 7))) * 16u;
            cpasync16(sbB + off, Bbase + (long)row * K + kk + ldC * 8);
        }
    };

    const int lrow = lane & 15;
    const int lcol = lane >> 4;

    load_tile(0, 0);
    cp_commit();
    load_tile(1, 1);
    cp_commit();

    for (int ch = 0; ch < nch; ch++) {
        if (ch + 2 < nch) {
            load_tile(ch + 2, (ch + 2) % 3);
            cp_commit();
            cp_wait<2>();
        } else if (ch + 1 < nch) {
            cp_wait<1>();
        } else {
            cp_wait<0>();
        }
        __syncthreads();

        const uint32_t sbA = sb + (ch % 3) * STAGE;
        const uint32_t sbB = sbA + TILE_A;

        uint32_t fa[2][4][4];
        uint32_t fb[2][NT][2];

        auto load_frags = [&](int ks, int pb) {
#pragma unroll
            for (int mt = 0; mt < 4; mt++) {
                int row = wm * 64 + mt * 16 + lrow;
                int c = 2 * ks + lcol;
                uint32_t addr = sbA + ((uint32_t)row * 8u + (uint32_t)(c ^ (row & 7))) * 16u;
                ldsm4(fa[pb][mt], addr);
            }
#pragma unroll
            for (int p = 0; p < NT / 2; p++) {
                int row = wn * (NTILE / 2) + p * 16 + lrow;
                int c = 2 * ks + lcol;
                uint32_t addr = sbB + ((uint32_t)row * 8u + (uint32_t)(c ^ (row & 7))) * 16u;
                uint32_t r[4];
                ldsm4(r, addr);
                fb[pb][2 * p][0] = r[0]; fb[pb][2 * p][1] = r[2];
                fb[pb][2 * p + 1][0] = r[1]; fb[pb][2 * p + 1][1] = r[3];
            }
        };

        load_frags(0, 0);
#pragma unroll
        for (int ks = 0; ks < 4; ks++) {             // 4 k16 steps in BK=64
            if (ks < 3) load_frags(ks + 1, (ks + 1) & 1);
#pragma unroll
            for (int mt = 0; mt < 4; mt++)
#pragma unroll
                for (int nt = 0; nt < NT; nt++)
                    mma16816(acc[mt][nt], fa[ks & 1][mt], fb[ks & 1][nt]);
        }
        __syncthreads();
    }

    // ---- epilogue ----
    const int g = lane >> 2, tg = lane & 3;
    if (EPI == 0) {
#pragma unroll
        for (int mt = 0; mt < 4; mt++) {
            long r0 = row0 + wm * 64 + mt * 16 + g;
#pragma unroll
            for (int nt = 0; nt < NT; nt++) {
                long cc = col0 + wn * (NTILE / 2) + nt * 8 + tg * 2;
                float2 v0 = make_float2(alpha * acc[mt][nt][0], alpha * acc[mt][nt][1]);
                float2 v1 = make_float2(alpha * acc[mt][nt][2], alpha * acc[mt][nt][3]);
                *reinterpret_cast<float2*>(Cbase + r0 * ldc + cc) = v0;
                *reinterpret_cast<float2*>(Cbase + (r0 + 8) * ldc + cc) = v1;
            }
        }
    } else {
        // merged QKV epilogue. n in [0,3072): Q | K | V
        const int nbase = (int)col0 + wn * (NTILE / 2) + tg * 2;
#pragma unroll
        for (int mt = 0; mt < 4; mt++) {
            long r0 = row0 + wm * 64 + mt * 16 + g;
#pragma unroll
            for (int nt = 0; nt < NT; nt++) {
                int n = nbase + nt * 8;
                if (n < 2048) {
                    int k = n & 1023;
                    int pidx = k >> 1;
#pragma unroll
                    for (int h = 0; h < 2; h++) {
                        long r = r0 + h * 8;
                        int m = (int)(r & (MM - 1));
                        float c = g_cos[(size_t)m * HALF_D + pidx];
                        float s = g_sin[(size_t)m * HALF_D + pidx];
                        float e = acc[mt][nt][2 * h], o = acc[mt][nt][2 * h + 1];
                        float re = e * c + o * s;
                        float ro = -e * s + o * c;
                        __half* dst = (n < 1024 ? g_Qh : g_Kh) + r * (long)DD + k;
                        *reinterpret_cast<__half2*>(dst) = __floats2half2_rn(re, ro);
                    }
                } else {
                    int k = n - 2048;
                    float2 v0 = make_float2(acc[mt][nt][0], acc[mt][nt][1]);
                    float2 v1 = make_float2(acc[mt][nt][2], acc[mt][nt][3]);
                    *reinterpret_cast<float2*>(g_Vf + r0 * DD + k) = v0;
                    *reinterpret_cast<float2*>(g_Vf + (r0 + 8) * DD + k) = v1;
                }
            }
        }
    }
}

// ---------------------------------------------------------------------------
// Launch.  Scores GEMM kept at launch index 5 for the ncu capture.
// ---------------------------------------------------------------------------
extern "C" void kernel_launch(void* const* d_in, const int* in_sizes, int n_in,
                              void* d_out, int out_size) {
    (void)in_sizes; (void)n_in; (void)out_size;
    const float* x  = (const float*)d_in[0];
    const float* wq = (const float*)d_in[1];
    const float* wk = (const float*)d_in[2];
    const float* wv = (const float*)d_in[3];
    float* out = (float*)d_out;

    __half *xh, *wh, *Qh, *Kh, *VhT, *Sh;
    float *Vf, *Sf;
    cudaGetSymbolAddress((void**)&xh, g_xh);
    cudaGetSymbolAddress((void**)&wh, g_wh);
    cudaGetSymbolAddress((void**)&Vf, g_Vf);
    cudaGetSymbolAddress((void**)&Qh, g_Qh);
    cudaGetSymbolAddress((void**)&Kh, g_Kh);
    cudaGetSymbolAddress((void**)&VhT, g_VhT);
    cudaGetSymbolAddress((void**)&Sf, g_Sf);
    cudaGetSymbolAddress((void**)&Sh, g_Sh);

    constexpr int SMEM128 = 3 * (128 * 64 * 2 + 128 * 64 * 2);   // 96 KB
    constexpr int SMEM64  = 3 * (128 * 64 * 2 + 64 * 64 * 2);    // 72 KB
    cudaFuncSetAttribute(mma_gemm_kernel<0, 128>, cudaFuncAttributeMaxDynamicSharedMemorySize, SMEM128);
    cudaFuncSetAttribute(mma_gemm_kernel<1, 128>, cudaFuncAttributeMaxDynamicSharedMemorySize, SMEM128);
    cudaFuncSetAttribute(mma_gemm_kernel<0, 64>,  cudaFuncAttributeMaxDynamicSharedMemorySize, SMEM64);

    // 0: RoPE tables
    rope_tables_kernel<<<(MM * HALF_D + 255) / 256, 256>>>();
    // 1: x -> fp16
    cvt_x_kernel<<<(int)(((long)ROWS * DD / 4 + 255) / 256), 256>>>(x, xh);
    // 2: weights -> fp16
    dim3 gW((DD * DD / 4 + 255) / 256, 1, 3);
    cvt_w_kernel<<<gW, 256>>>(wq, wk, wv, wh);

    // 3: Merged QKV projection with fused RoPE epilogue (K=1024)
    dim3 gProj(3 * DD / 128, ROWS / 128, 1);
    mma_gemm_kernel<1, 128><<<gProj, 128, SMEM128>>>(xh, wh, nullptr, DD, 0, 0, 0, 0, 1.0f);

    // 4: V transpose -> fp16
    dim3 gV(DD / 32, MM / 32, BB);
    vT_cvt_kernel<<<gV, dim3(32, 8)>>>(Vf, VhT);

    // 5: scores = Qr @ Kr^T / 32   <- ncu capture target (K=1024)
    dim3 gScore(MM / 128, MM / 128, BB);
    mma_gemm_kernel<0, 128><<<gScore, 128, SMEM128>>>(Qh, Kh, Sf, DD, MM,
                                                      (long)MM * DD, (long)MM * DD,
                                                      (long)MM * MM, 0.03125f);

    // 6: softmax -> fp16
    softmax_cvt_kernel<<<BB * MM, 256>>>(Sf, Sh);

    // 7: out = attn @ V  (K=2048, 128x64 tiles)
    dim3 gOut(DD / 64, MM / 128, BB);
    mma_gemm_kernel<0, 64><<<gOut, 128, SMEM64>>>(Sh, VhT, out, MM, DD,
                                                  (long)MM * MM, (long)DD * MM,
                                                  (long)MM * DD, 1.0f);
}

// round 10
// speedup vs baseline: 2.3187x; 1.0107x over previous
#include <cuda_runtime.h>
#include <cuda_fp16.h>
#include <math.h>
#include <stdint.h>

// Problem dims (fixed)
#define BB 8
#define MM 2048
#define DD 1024
#define HALF_D 512
#define ROWS 16384           // BB*MM

// ---------------------------------------------------------------------------
// Device-global scratch (allocation-free, graph-capture safe). Plain fp16.
// ---------------------------------------------------------------------------
__device__ __half g_xh[(size_t)ROWS * DD];        // x fp16
__device__ __half g_wh[(size_t)(3 * DD) * DD];    // [wq;wk;wv] fp16
__device__ __half g_Qh[(size_t)ROWS * DD];        // rotated Q fp16
__device__ __half g_Kh[(size_t)ROWS * DD];        // rotated K fp16
__device__ __half g_VhT[(size_t)BB * DD * MM];    // V^T fp16 (written by proj epilogue)
__device__ float g_Sf[(size_t)BB * MM * MM];      // scores fp32
__device__ __half g_Sh[(size_t)BB * MM * MM];     // attn fp16
__device__ float2 g_cs[(size_t)MM * HALF_D];      // interleaved {cos, sin}

// ---------------------------------------------------------------------------
// PTX helpers (base-ISA: mma.sync / ldmatrix / cp.async)
// ---------------------------------------------------------------------------
__device__ __forceinline__ uint32_t smem_u32(const void* p) {
    uint32_t a;
    asm("{ .reg .u64 t; cvta.to.shared.u64 t, %1; cvt.u32.u64 %0, t; }" : "=r"(a) : "l"(p));
    return a;
}
__device__ __forceinline__ void mma16816(float* d, const uint32_t* a, const uint32_t* b) {
    asm volatile(
        "mma.sync.aligned.m16n8k16.row.col.f32.f16.f16.f32 "
        "{%0,%1,%2,%3}, {%4,%5,%6,%7}, {%8,%9}, {%0,%1,%2,%3};"
        : "+f"(d[0]), "+f"(d[1]), "+f"(d[2]), "+f"(d[3])
        : "r"(a[0]), "r"(a[1]), "r"(a[2]), "r"(a[3]), "r"(b[0]), "r"(b[1]));
}
__device__ __forceinline__ void ldsm4(uint32_t* r, uint32_t addr) {
    asm volatile("ldmatrix.sync.aligned.m8n8.x4.shared.b16 {%0,%1,%2,%3}, [%4];"
                 : "=r"(r[0]), "=r"(r[1]), "=r"(r[2]), "=r"(r[3]) : "r"(addr));
}
__device__ __forceinline__ void cpasync16(uint32_t dst, const void* src) {
    asm volatile("cp.async.cg.shared.global [%0], [%1], 16;" :: "r"(dst), "l"(src));
}
__device__ __forceinline__ void cp_commit() {
    asm volatile("cp.async.commit_group;" ::: "memory");
}
template <int N>
__device__ __forceinline__ void cp_wait() {
    asm volatile("cp.async.wait_group %0;" :: "n"(N) : "memory");
}

// ---------------------------------------------------------------------------
// RoPE tables (interleaved cos/sin)
// ---------------------------------------------------------------------------
__global__ void rope_tables_kernel() {
    int idx = blockIdx.x * blockDim.x + threadIdx.x;
    if (idx >= MM * HALF_D) return;
    int m = idx / HALF_D;
    int i = idx % HALF_D;
    double theta_d = pow(10000.0, -2.0 * ((double)i - 1.0) / (double)DD);
    float ang = (float)m * (float)theta_d;
    g_cs[idx] = make_float2(cosf(ang), sinf(ang));
}

// ---------------------------------------------------------------------------
// fp32 -> fp16 for x
// ---------------------------------------------------------------------------
__global__ void cvt_x_kernel(const float* __restrict__ src, __half* __restrict__ dst) {
    long idx = ((long)blockIdx.x * blockDim.x + threadIdx.x) * 4;
    if (idx >= (long)ROWS * DD) return;
    float4 v = *reinterpret_cast<const float4*>(src + idx);
    *reinterpret_cast<__half2*>(dst + idx)     = __floats2half2_rn(v.x, v.y);
    *reinterpret_cast<__half2*>(dst + idx + 2) = __floats2half2_rn(v.z, v.w);
}

// ---------------------------------------------------------------------------
// All three weights -> fp16 in one launch (z selects w)
// ---------------------------------------------------------------------------
__global__ void cvt_w_kernel(const float* __restrict__ wq, const float* __restrict__ wk,
                             const float* __restrict__ wv, __half* __restrict__ dst) {
    long idx = ((long)blockIdx.x * blockDim.x + threadIdx.x) * 4;
    if (idx >= (long)DD * DD) return;
    const float* src = blockIdx.z == 0 ? wq : (blockIdx.z == 1 ? wk : wv);
    float4 v = *reinterpret_cast<const float4*>(src + idx);
    __half* r = dst + (long)blockIdx.z * DD * DD + idx;
    *reinterpret_cast<__half2*>(r)     = __floats2half2_rn(v.x, v.y);
    *reinterpret_cast<__half2*>(r + 2) = __floats2half2_rn(v.z, v.w);
}

// ---------------------------------------------------------------------------
// Row softmax (len MM), shuffle reductions, fused fp16 conversion
// ---------------------------------------------------------------------------
__global__ void __launch_bounds__(256) softmax_cvt_kernel(const float* __restrict__ S,
                                                          __half* __restrict__ Sh) {
    __shared__ float sm[8];
    long row = blockIdx.x;
    const float4* p = reinterpret_cast<const float4*>(S + row * (long)MM);
    int t = threadIdx.x;
    float4 v0 = p[t];
    float4 v1 = p[t + 256];

    float mx = fmaxf(fmaxf(fmaxf(v0.x, v0.y), fmaxf(v0.z, v0.w)),
                     fmaxf(fmaxf(v1.x, v1.y), fmaxf(v1.z, v1.w)));
#pragma unroll
    for (int o = 16; o > 0; o >>= 1) mx = fmaxf(mx, __shfl_xor_sync(0xffffffffu, mx, o));
    if ((t & 31) == 0) sm[t >> 5] = mx;
    __syncthreads();
    mx = fmaxf(fmaxf(fmaxf(sm[0], sm[1]), fmaxf(sm[2], sm[3])),
               fmaxf(fmaxf(sm[4], sm[5]), fmaxf(sm[6], sm[7])));

    v0.x = expf(v0.x - mx); v0.y = expf(v0.y - mx);
    v0.z = expf(v0.z - mx); v0.w = expf(v0.w - mx);
    v1.x = expf(v1.x - mx); v1.y = expf(v1.y - mx);
    v1.z = expf(v1.z - mx); v1.w = expf(v1.w - mx);

    float sum = (v0.x + v0.y + v0.z + v0.w) + (v1.x + v1.y + v1.z + v1.w);
#pragma unroll
    for (int o = 16; o > 0; o >>= 1) sum += __shfl_xor_sync(0xffffffffu, sum, o);
    __syncthreads();                    // sm reuse: all max-reads done
    if ((t & 31) == 0) sm[t >> 5] = sum;
    __syncthreads();
    float inv = 1.0f / (sm[0] + sm[1] + sm[2] + sm[3] + sm[4] + sm[5] + sm[6] + sm[7]);

    __half* r = Sh + row * (long)MM;
    *reinterpret_cast<__half2*>(r + 4 * t)            = __floats2half2_rn(v0.x * inv, v0.y * inv);
    *reinterpret_cast<__half2*>(r + 4 * t + 2)        = __floats2half2_rn(v0.z * inv, v0.w * inv);
    *reinterpret_cast<__half2*>(r + 1024 + 4 * t)     = __floats2half2_rn(v1.x * inv, v1.y * inv);
    *reinterpret_cast<__half2*>(r + 1024 + 4 * t + 2) = __floats2half2_rn(v1.z * inv, v1.w * inv);
}

// ---------------------------------------------------------------------------
// mma.sync fp16 GEMM (NT, both operands K-major).
// CTA tile 128 x NTILE, BK=64, 3-stage cp.async, XOR swizzle, 4 warps (2Mx2N),
// register fragment double-buffering.
//   EPI=0: C = alpha * A x B^T (fp32)
//   EPI=1 (NTILE=128): merged QKV epilogue — Q/K RoPE'd fp16; V written
//                      directly transposed fp16 into g_VhT
// ---------------------------------------------------------------------------
template <int EPI, int NTILE>
__global__ void __launch_bounds__(128, NTILE == 64 ? 3 : 2) mma_gemm_kernel(
    const __half* __restrict__ A, const __half* __restrict__ B,
    float* __restrict__ C, int K, int ldc, long sA, long sB, long sC, float alpha)
{
    constexpr int NT = NTILE / 16;            // n8 tiles per warp (8 or 4)
    constexpr int TILE_A = 128 * 64 * 2;      // 16 KB
    constexpr int TILE_B = NTILE * 64 * 2;    // 16 or 8 KB
    constexpr int STAGE = TILE_A + TILE_B;

    extern __shared__ char smem[];
    const uint32_t sb = smem_u32(smem);
    const int tid = threadIdx.x;
    const int wid = tid >> 5, lane = tid & 31;
    const int wm = wid & 1;          // warp M index (x64 rows)
    const int wn = wid >> 1;         // warp N index (x NTILE/2 cols)

    const long row0 = (long)blockIdx.y * 128;
    const long col0 = (long)blockIdx.x * NTILE;
    const __half* Abase = A + blockIdx.z * sA + row0 * K;
    const __half* Bbase = B + blockIdx.z * sB + col0 * K;
    float* Cbase = C + blockIdx.z * sC;

    const int ldRow = tid >> 3;      // rows 0..15 (+16*i)
    const int ldC = tid & 7;         // 16B chunk within 128B row

    float acc[4][NT][4];
#pragma unroll
    for (int i = 0; i < 4; i++)
#pragma unroll
        for (int j = 0; j < NT; j++)
#pragma unroll
            for (int q = 0; q < 4; q++) acc[i][j][q] = 0.0f;

    const int nch = K >> 6;

    auto load_tile = [&](int ch, int buf) {
        const int kk = ch << 6;
        const uint32_t sbA = sb + buf * STAGE;
        const uint32_t sbB = sbA + TILE_A;
#pragma unroll
        for (int i = 0; i < 8; i++) {
            int row = ldRow + i * 16;
            uint32_t off = ((uint32_t)row * 8u + (uint32_t)(ldC ^ (row & 7))) * 16u;
            cpasync16(sbA + off, Abase + (long)row * K + kk + ldC * 8);
        }
#pragma unroll
        for (int i = 0; i < NTILE / 16; i++) {
            int row = ldRow + i * 16;
            uint32_t off = ((uint32_t)row * 8u + (uint32_t)(ldC ^ (row & 7))) * 16u;
            cpasync16(sbB + off, Bbase + (long)row * K + kk + ldC * 8);
        }
    };

    const int lrow = lane & 15;
    const int lcol = lane >> 4;

    load_tile(0, 0);
    cp_commit();
    load_tile(1, 1);
    cp_commit();

    for (int ch = 0; ch < nch; ch++) {
        if (ch + 2 < nch) {
            load_tile(ch + 2, (ch + 2) % 3);
            cp_commit();
            cp_wait<2>();
        } else if (ch + 1 < nch) {
            cp_wait<1>();
        } else {
            cp_wait<0>();
        }
        __syncthreads();

        const uint32_t sbA = sb + (ch % 3) * STAGE;
        const uint32_t sbB = sbA + TILE_A;

        uint32_t fa[2][4][4];
        uint32_t fb[2][NT][2];

        auto load_frags = [&](int ks, int pb) {
#pragma unroll
            for (int mt = 0; mt < 4; mt++) {
                int row = wm * 64 + mt * 16 + lrow;
                int c = 2 * ks + lcol;
                uint32_t addr = sbA + ((uint32_t)row * 8u + (uint32_t)(c ^ (row & 7))) * 16u;
                ldsm4(fa[pb][mt], addr);
            }
#pragma unroll
            for (int p = 0; p < NT / 2; p++) {
                int row = wn * (NTILE / 2) + p * 16 + lrow;
                int c = 2 * ks + lcol;
                uint32_t addr = sbB + ((uint32_t)row * 8u + (uint32_t)(c ^ (row & 7))) * 16u;
                uint32_t r[4];
                ldsm4(r, addr);
                fb[pb][2 * p][0] = r[0]; fb[pb][2 * p][1] = r[2];
                fb[pb][2 * p + 1][0] = r[1]; fb[pb][2 * p + 1][1] = r[3];
            }
        };

        load_frags(0, 0);
#pragma unroll
        for (int ks = 0; ks < 4; ks++) {             // 4 k16 steps in BK=64
            if (ks < 3) load_frags(ks + 1, (ks + 1) & 1);
#pragma unroll
            for (int mt = 0; mt < 4; mt++)
#pragma unroll
                for (int nt = 0; nt < NT; nt++)
                    mma16816(acc[mt][nt], fa[ks & 1][mt], fb[ks & 1][nt]);
        }
        __syncthreads();
    }

    // ---- epilogue ----
    const int g = lane >> 2, tg = lane & 3;
    if (EPI == 0) {
#pragma unroll
        for (int mt = 0; mt < 4; mt++) {
            long r0 = row0 + wm * 64 + mt * 16 + g;
#pragma unroll
            for (int nt = 0; nt < NT; nt++) {
                long cc = col0 + wn * (NTILE / 2) + nt * 8 + tg * 2;
                float2 v0 = make_float2(alpha * acc[mt][nt][0], alpha * acc[mt][nt][1]);
                float2 v1 = make_float2(alpha * acc[mt][nt][2], alpha * acc[mt][nt][3]);
                *reinterpret_cast<float2*>(Cbase + r0 * ldc + cc) = v0;
                *reinterpret_cast<float2*>(Cbase + (r0 + 8) * ldc + cc) = v1;
            }
        }
    } else {
        // merged QKV epilogue. n in [0,3072): Q | K | V
        const int nbase = (int)col0 + wn * (NTILE / 2) + tg * 2;
#pragma unroll
        for (int mt = 0; mt < 4; mt++) {
            long r0 = row0 + wm * 64 + mt * 16 + g;
#pragma unroll
            for (int nt = 0; nt < NT; nt++) {
                int n = nbase + nt * 8;
                if (n < 2048) {
                    int k = n & 1023;
                    int pidx = k >> 1;
#pragma unroll
                    for (int h = 0; h < 2; h++) {
                        long r = r0 + h * 8;
                        int m = (int)(r & (MM - 1));
                        float2 cs = g_cs[(size_t)m * HALF_D + pidx];
                        float e = acc[mt][nt][2 * h], o = acc[mt][nt][2 * h + 1];
                        float re = e * cs.x + o * cs.y;
                        float ro = -e * cs.y + o * cs.x;
                        __half* dst = (n < 1024 ? g_Qh : g_Kh) + r * (long)DD + k;
                        *reinterpret_cast<__half2*>(dst) = __floats2half2_rn(re, ro);
                    }
                } else {
                    int vcol = n - 2048;
#pragma unroll
                    for (int h = 0; h < 2; h++) {
                        long r = r0 + h * 8;
                        int b = (int)(r >> 11);          // r / MM
                        int m = (int)(r & (MM - 1));
                        __half* dst = g_VhT + ((long)(b * DD + vcol)) * MM + m;
                        dst[0]  = __float2half(acc[mt][nt][2 * h]);
                        dst[MM] = __float2half(acc[mt][nt][2 * h + 1]);   // vcol+1
                    }
                }
            }
        }
    }
}

// ---------------------------------------------------------------------------
// Launch.  Softmax sits at launch index 5 for the ncu capture this round.
// ---------------------------------------------------------------------------
extern "C" void kernel_launch(void* const* d_in, const int* in_sizes, int n_in,
                              void* d_out, int out_size) {
    (void)in_sizes; (void)n_in; (void)out_size;
    const float* x  = (const float*)d_in[0];
    const float* wq = (const float*)d_in[1];
    const float* wk = (const float*)d_in[2];
    const float* wv = (const float*)d_in[3];
    float* out = (float*)d_out;

    __half *xh, *wh, *Qh, *Kh, *VhT, *Sh;
    float *Sf;
    cudaGetSymbolAddress((void**)&xh, g_xh);
    cudaGetSymbolAddress((void**)&wh, g_wh);
    cudaGetSymbolAddress((void**)&Qh, g_Qh);
    cudaGetSymbolAddress((void**)&Kh, g_Kh);
    cudaGetSymbolAddress((void**)&VhT, g_VhT);
    cudaGetSymbolAddress((void**)&Sf, g_Sf);
    cudaGetSymbolAddress((void**)&Sh, g_Sh);

    constexpr int SMEM128 = 3 * (128 * 64 * 2 + 128 * 64 * 2);   // 96 KB
    constexpr int SMEM64  = 3 * (128 * 64 * 2 + 64 * 64 * 2);    // 72 KB
    cudaFuncSetAttribute(mma_gemm_kernel<0, 128>, cudaFuncAttributeMaxDynamicSharedMemorySize, SMEM128);
    cudaFuncSetAttribute(mma_gemm_kernel<1, 128>, cudaFuncAttributeMaxDynamicSharedMemorySize, SMEM128);
    cudaFuncSetAttribute(mma_gemm_kernel<0, 64>,  cudaFuncAttributeMaxDynamicSharedMemorySize, SMEM64);

    // 0: RoPE tables
    rope_tables_kernel<<<(MM * HALF_D + 255) / 256, 256>>>();
    // 1: x -> fp16
    cvt_x_kernel<<<(int)(((long)ROWS * DD / 4 + 255) / 256), 256>>>(x, xh);
    // 2: weights -> fp16
    dim3 gW((DD * DD / 4 + 255) / 256, 1, 3);
    cvt_w_kernel<<<gW, 256>>>(wq, wk, wv, wh);

    // 3: Merged QKV projection; epilogue emits Qh/Kh (RoPE) and VhT (transposed)
    dim3 gProj(3 * DD / 128, ROWS / 128, 1);
    mma_gemm_kernel<1, 128><<<gProj, 128, SMEM128>>>(xh, wh, nullptr, DD, 0, 0, 0, 0, 1.0f);

    // 4: scores = Qr @ Kr^T / 32   (K=1024)
    dim3 gScore(MM / 128, MM / 128, BB);
    mma_gemm_kernel<0, 128><<<gScore, 128, SMEM128>>>(Qh, Kh, Sf, DD, MM,
                                                      (long)MM * DD, (long)MM * DD,
                                                      (long)MM * MM, 0.03125f);

    // 5: softmax -> fp16   <- ncu capture target
    softmax_cvt_kernel<<<BB * MM, 256>>>(Sf, Sh);

    // 6: out = attn @ V  (K=2048, 128x64 tiles)
    dim3 gOut(DD / 64, MM / 128, BB);
    mma_gemm_kernel<0, 64><<<gOut, 128, SMEM64>>>(Sh, VhT, out, MM, DD,
                                                  (long)MM * MM, (long)DD * MM,
                                                  (long)MM * DD, 1.0f);
}

// round 11
// speedup vs baseline: 2.4030x; 1.0364x over previous
#include <cuda_runtime.h>
#include <cuda_fp16.h>
#include <math.h>
#include <stdint.h>

// Problem dims (fixed)
#define BB 8
#define MM 2048
#define DD 1024
#define HALF_D 512
#define ROWS 16384           // BB*MM

// ---------------------------------------------------------------------------
// Device-global scratch (allocation-free, graph-capture safe). Plain fp16.
// ---------------------------------------------------------------------------
__device__ __half g_xh[(size_t)ROWS * DD];        // x fp16
__device__ __half g_wh[(size_t)(3 * DD) * DD];    // [wq;wk;wv] fp16
__device__ __half g_Qh[(size_t)ROWS * DD];        // rotated Q fp16
__device__ __half g_Kh[(size_t)ROWS * DD];        // rotated K fp16
__device__ __half g_VhT[(size_t)BB * DD * MM];    // V^T fp16 (from proj epilogue)
__device__ __half g_Eh[(size_t)BB * MM * MM];     // exp(scores) fp16
__device__ float g_psum[(size_t)ROWS * 32];       // per-row exp partial sums
__device__ float2 g_cs[(size_t)MM * HALF_D];      // interleaved {cos, sin}

// ---------------------------------------------------------------------------
// PTX helpers (base-ISA: mma.sync / ldmatrix / cp.async)
// ---------------------------------------------------------------------------
__device__ __forceinline__ uint32_t smem_u32(const void* p) {
    uint32_t a;
    asm("{ .reg .u64 t; cvta.to.shared.u64 t, %1; cvt.u32.u64 %0, t; }" : "=r"(a) : "l"(p));
    return a;
}
__device__ __forceinline__ void mma16816(float* d, const uint32_t* a, const uint32_t* b) {
    asm volatile(
        "mma.sync.aligned.m16n8k16.row.col.f32.f16.f16.f32 "
        "{%0,%1,%2,%3}, {%4,%5,%6,%7}, {%8,%9}, {%0,%1,%2,%3};"
        : "+f"(d[0]), "+f"(d[1]), "+f"(d[2]), "+f"(d[3])
        : "r"(a[0]), "r"(a[1]), "r"(a[2]), "r"(a[3]), "r"(b[0]), "r"(b[1]));
}
__device__ __forceinline__ void ldsm4(uint32_t* r, uint32_t addr) {
    asm volatile("ldmatrix.sync.aligned.m8n8.x4.shared.b16 {%0,%1,%2,%3}, [%4];"
                 : "=r"(r[0]), "=r"(r[1]), "=r"(r[2]), "=r"(r[3]) : "r"(addr));
}
__device__ __forceinline__ void cpasync16(uint32_t dst, const void* src) {
    asm volatile("cp.async.cg.shared.global [%0], [%1], 16;" :: "r"(dst), "l"(src));
}
__device__ __forceinline__ void cp_commit() {
    asm volatile("cp.async.commit_group;" ::: "memory");
}
template <int N>
__device__ __forceinline__ void cp_wait() {
    asm volatile("cp.async.wait_group %0;" :: "n"(N) : "memory");
}

// ---------------------------------------------------------------------------
// RoPE tables (interleaved cos/sin)
// ---------------------------------------------------------------------------
__global__ void rope_tables_kernel() {
    int idx = blockIdx.x * blockDim.x + threadIdx.x;
    if (idx >= MM * HALF_D) return;
    int m = idx / HALF_D;
    int i = idx % HALF_D;
    double theta_d = pow(10000.0, -2.0 * ((double)i - 1.0) / (double)DD);
    float ang = (float)m * (float)theta_d;
    g_cs[idx] = make_float2(cosf(ang), sinf(ang));
}

// ---------------------------------------------------------------------------
// fp32 -> fp16 for x
// ---------------------------------------------------------------------------
__global__ void cvt_x_kernel(const float* __restrict__ src, __half* __restrict__ dst) {
    long idx = ((long)blockIdx.x * blockDim.x + threadIdx.x) * 4;
    if (idx >= (long)ROWS * DD) return;
    float4 v = *reinterpret_cast<const float4*>(src + idx);
    *reinterpret_cast<__half2*>(dst + idx)     = __floats2half2_rn(v.x, v.y);
    *reinterpret_cast<__half2*>(dst + idx + 2) = __floats2half2_rn(v.z, v.w);
}

// ---------------------------------------------------------------------------
// All three weights -> fp16 in one launch (z selects w)
// ---------------------------------------------------------------------------
__global__ void cvt_w_kernel(const float* __restrict__ wq, const float* __restrict__ wk,
                             const float* __restrict__ wv, __half* __restrict__ dst) {
    long idx = ((long)blockIdx.x * blockDim.x + threadIdx.x) * 4;
    if (idx >= (long)DD * DD) return;
    const float* src = blockIdx.z == 0 ? wq : (blockIdx.z == 1 ? wk : wv);
    float4 v = *reinterpret_cast<const float4*>(src + idx);
    __half* r = dst + (long)blockIdx.z * DD * DD + idx;
    *reinterpret_cast<__half2*>(r)     = __floats2half2_rn(v.x, v.y);
    *reinterpret_cast<__half2*>(r + 2) = __floats2half2_rn(v.z, v.w);
}

// ---------------------------------------------------------------------------
// mma.sync fp16 GEMM (NT, both operands K-major).
// CTA tile 128 x NTILE, BK=64, 3-stage cp.async, XOR swizzle, 4 warps (2Mx2N),
// register fragment double-buffering.
//   EPI=1 (NTILE=128): merged QKV projection epilogue
//       cols [0,2048): RoPE -> g_Qh / g_Kh (fp16)
//       cols [2048,3072): smem-transpose -> g_VhT (fp16, coalesced)
//   EPI=2 (NTILE=128): scores epilogue: e = expf(alpha*s) -> g_Eh (fp16),
//       deterministic per-(row, 64-col slab) partial sums -> g_psum
//   EPI=3 (NTILE=64): PV epilogue: scale rows by 1/rowsum(g_psum), fp32 out
// ---------------------------------------------------------------------------
template <int EPI, int NTILE>
__global__ void __launch_bounds__(128, NTILE == 64 ? 3 : 2) mma_gemm_kernel(
    const __half* __restrict__ A, const __half* __restrict__ B,
    float* __restrict__ C, int K, int ldc, long sA, long sB, long sC, float alpha)
{
    constexpr int NT = NTILE / 16;            // n8 tiles per warp (8 or 4)
    constexpr int TILE_A = 128 * 64 * 2;      // 16 KB
    constexpr int TILE_B = NTILE * 64 * 2;    // 16 or 8 KB
    constexpr int STAGE = TILE_A + TILE_B;

    extern __shared__ char smem[];
    const uint32_t sb = smem_u32(smem);
    const int tid = threadIdx.x;
    const int wid = tid >> 5, lane = tid & 31;
    const int wm = wid & 1;          // warp M index (x64 rows)
    const int wn = wid >> 1;         // warp N index (x NTILE/2 cols)

    const long row0 = (long)blockIdx.y * 128;
    const long col0 = (long)blockIdx.x * NTILE;
    const __half* Abase = A + blockIdx.z * sA + row0 * K;
    const __half* Bbase = B + blockIdx.z * sB + col0 * K;
    float* Cbase = C + blockIdx.z * sC;

    const int ldRow = tid >> 3;      // rows 0..15 (+16*i)
    const int ldC = tid & 7;         // 16B chunk within 128B row

    float acc[4][NT][4];
#pragma unroll
    for (int i = 0; i < 4; i++)
#pragma unroll
        for (int j = 0; j < NT; j++)
#pragma unroll
            for (int q = 0; q < 4; q++) acc[i][j][q] = 0.0f;

    const int nch = K >> 6;

    auto load_tile = [&](int ch, int buf) {
        const int kk = ch << 6;
        const uint32_t sbA = sb + buf * STAGE;
        const uint32_t sbB = sbA + TILE_A;
#pragma unroll
        for (int i = 0; i < 8; i++) {
            int row = ldRow + i * 16;
            uint32_t off = ((uint32_t)row * 8u + (uint32_t)(ldC ^ (row & 7))) * 16u;
            cpasync16(sbA + off, Abase + (long)row * K + kk + ldC * 8);
        }
#pragma unroll
        for (int i = 0; i < NTILE / 16; i++) {
            int row = ldRow + i * 16;
            uint32_t off = ((uint32_t)row * 8u + (uint32_t)(ldC ^ (row & 7))) * 16u;
            cpasync16(sbB + off, Bbase + (long)row * K + kk + ldC * 8);
        }
    };

    const int lrow = lane & 15;
    const int lcol = lane >> 4;

    load_tile(0, 0);
    cp_commit();
    load_tile(1, 1);
    cp_commit();

    for (int ch = 0; ch < nch; ch++) {
        if (ch + 2 < nch) {
            load_tile(ch + 2, (ch + 2) % 3);
            cp_commit();
            cp_wait<2>();
        } else if (ch + 1 < nch) {
            cp_wait<1>();
        } else {
            cp_wait<0>();
        }
        __syncthreads();

        const uint32_t sbA = sb + (ch % 3) * STAGE;
        const uint32_t sbB = sbA + TILE_A;

        uint32_t fa[2][4][4];
        uint32_t fb[2][NT][2];

        auto load_frags = [&](int ks, int pb) {
#pragma unroll
            for (int mt = 0; mt < 4; mt++) {
                int row = wm * 64 + mt * 16 + lrow;
                int c = 2 * ks + lcol;
                uint32_t addr = sbA + ((uint32_t)row * 8u + (uint32_t)(c ^ (row & 7))) * 16u;
                ldsm4(fa[pb][mt], addr);
            }
#pragma unroll
            for (int p = 0; p < NT / 2; p++) {
                int row = wn * (NTILE / 2) + p * 16 + lrow;
                int c = 2 * ks + lcol;
                uint32_t addr = sbB + ((uint32_t)row * 8u + (uint32_t)(c ^ (row & 7))) * 16u;
                uint32_t r[4];
                ldsm4(r, addr);
                fb[pb][2 * p][0] = r[0]; fb[pb][2 * p][1] = r[2];
                fb[pb][2 * p + 1][0] = r[1]; fb[pb][2 * p + 1][1] = r[3];
            }
        };

        load_frags(0, 0);
#pragma unroll
        for (int ks = 0; ks < 4; ks++) {             // 4 k16 steps in BK=64
            if (ks < 3) load_frags(ks + 1, (ks + 1) & 1);
#pragma unroll
            for (int mt = 0; mt < 4; mt++)
#pragma unroll
                for (int nt = 0; nt < NT; nt++)
                    mma16816(acc[mt][nt], fa[ks & 1][mt], fb[ks & 1][nt]);
        }
        __syncthreads();
    }

    // ---- epilogue ----
    const int g = lane >> 2, tg = lane & 3;

    if (EPI == 1) {
        // merged QKV epilogue. n in [0,3072): Q | K | V
        if (col0 < 2048) {
            const int nbase = (int)col0 + wn * 64 + tg * 2;
#pragma unroll
            for (int mt = 0; mt < 4; mt++) {
                long r0 = row0 + wm * 64 + mt * 16 + g;
#pragma unroll
                for (int nt = 0; nt < NT; nt++) {
                    int n = nbase + nt * 8;
                    int k = n & 1023;
                    int pidx = k >> 1;
#pragma unroll
                    for (int h = 0; h < 2; h++) {
                        long r = r0 + h * 8;
                        int m = (int)(r & (MM - 1));
                        float2 cs = g_cs[(size_t)m * HALF_D + pidx];
                        float e = acc[mt][nt][2 * h], o = acc[mt][nt][2 * h + 1];
                        float re = e * cs.x + o * cs.y;
                        float ro = -e * cs.y + o * cs.x;
                        __half* dst = (n < 1024 ? g_Qh : g_Kh) + r * (long)DD + k;
                        *reinterpret_cast<__half2*>(dst) = __floats2half2_rn(re, ro);
                    }
                }
            }
        } else {
            // V tile: transpose through smem, coalesced fp16 stores along M
            __half* sv = reinterpret_cast<__half*>(smem);
            const int RS = 136;                    // padded row stride (halfs)
#pragma unroll
            for (int mt = 0; mt < 4; mt++)
#pragma unroll
                for (int nt = 0; nt < NT; nt++) {
                    int cl = wn * 64 + nt * 8 + tg * 2;
#pragma unroll
                    for (int h = 0; h < 2; h++) {
                        int rl = wm * 64 + mt * 16 + g + h * 8;
                        *reinterpret_cast<__half2*>(&sv[rl * RS + cl]) =
                            __floats2half2_rn(acc[mt][nt][2 * h], acc[mt][nt][2 * h + 1]);
                    }
                }
            __syncthreads();
            int b = (int)(row0 >> 11);
            int m0 = (int)(row0 & (MM - 1));
            int vcol = (int)col0 - 2048 + tid;     // one column per thread
            __half* dst = g_VhT + ((long)(b * DD + vcol)) * MM + m0;
#pragma unroll
            for (int c8 = 0; c8 < 16; c8++) {
                __half tmp[8];
#pragma unroll
                for (int j = 0; j < 8; j++) tmp[j] = sv[(c8 * 8 + j) * RS + tid];
                *reinterpret_cast<uint4*>(dst + c8 * 8) = *reinterpret_cast<uint4*>(tmp);
            }
        }
    } else if (EPI == 2) {
        // scores epilogue: e = expf(alpha*s) -> fp16, partial row sums
        __half* Eb = g_Eh + (long)blockIdx.z * MM * MM;
        float rs[4][2];
#pragma unroll
        for (int mt = 0; mt < 4; mt++) { rs[mt][0] = 0.0f; rs[mt][1] = 0.0f; }
#pragma unroll
        for (int mt = 0; mt < 4; mt++) {
            long r0 = row0 + wm * 64 + mt * 16 + g;
#pragma unroll
            for (int nt = 0; nt < NT; nt++) {
                long cc = col0 + wn * 64 + nt * 8 + tg * 2;
#pragma unroll
                for (int h = 0; h < 2; h++) {
                    float e0 = expf(alpha * acc[mt][nt][2 * h]);
                    float e1 = expf(alpha * acc[mt][nt][2 * h + 1]);
                    *reinterpret_cast<__half2*>(Eb + (r0 + h * 8) * MM + cc) =
                        __floats2half2_rn(e0, e1);
                    rs[mt][h] += e0 + e1;
                }
            }
        }
        // reduce across tg (lanes 0..3 within each row group)
#pragma unroll
        for (int mt = 0; mt < 4; mt++)
#pragma unroll
            for (int h = 0; h < 2; h++) {
                float v = rs[mt][h];
                v += __shfl_xor_sync(0xffffffffu, v, 1);
                v += __shfl_xor_sync(0xffffffffu, v, 2);
                rs[mt][h] = v;
            }
        if (tg == 0) {
#pragma unroll
            for (int mt = 0; mt < 4; mt++)
#pragma unroll
                for (int h = 0; h < 2; h++) {
                    long rr = row0 + wm * 64 + mt * 16 + g + h * 8;
                    g_psum[((long)blockIdx.z * MM + rr) * 32 + blockIdx.x * 2 + wn] = rs[mt][h];
                }
        }
    } else {
        // EPI == 3: PV epilogue — divide by row sums
        __shared__ float s_inv[128];
        {
            const float4* pp = reinterpret_cast<const float4*>(
                g_psum + ((long)blockIdx.z * MM + row0 + tid) * 32);
            float s = 0.0f;
#pragma unroll
            for (int q = 0; q < 8; q++) {
                float4 v = pp[q];
                s += (v.x + v.y) + (v.z + v.w);
            }
            s_inv[tid] = 1.0f / s;
        }
        __syncthreads();
#pragma unroll
        for (int mt = 0; mt < 4; mt++) {
            int l0 = wm * 64 + mt * 16 + g;
            long r0 = row0 + l0;
            float inv0 = s_inv[l0];
            float inv1 = s_inv[l0 + 8];
#pragma unroll
            for (int nt = 0; nt < NT; nt++) {
                long cc = col0 + wn * (NTILE / 2) + nt * 8 + tg * 2;
                float2 v0 = make_float2(acc[mt][nt][0] * inv0, acc[mt][nt][1] * inv0);
                float2 v1 = make_float2(acc[mt][nt][2] * inv1, acc[mt][nt][3] * inv1);
                *reinterpret_cast<float2*>(Cbase + r0 * ldc + cc) = v0;
                *reinterpret_cast<float2*>(Cbase + (r0 + 8) * ldc + cc) = v1;
            }
        }
    }
}

// ---------------------------------------------------------------------------
// Launch. 6 kernels: tables, cvt_x, cvt_w, proj, scores, PV.
// ---------------------------------------------------------------------------
extern "C" void kernel_launch(void* const* d_in, const int* in_sizes, int n_in,
                              void* d_out, int out_size) {
    (void)in_sizes; (void)n_in; (void)out_size;
    const float* x  = (const float*)d_in[0];
    const float* wq = (const float*)d_in[1];
    const float* wk = (const float*)d_in[2];
    const float* wv = (const float*)d_in[3];
    float* out = (float*)d_out;

    __half *xh, *wh, *Qh, *Kh, *VhT, *Eh;
    cudaGetSymbolAddress((void**)&xh, g_xh);
    cudaGetSymbolAddress((void**)&wh, g_wh);
    cudaGetSymbolAddress((void**)&Qh, g_Qh);
    cudaGetSymbolAddress((void**)&Kh, g_Kh);
    cudaGetSymbolAddress((void**)&VhT, g_VhT);
    cudaGetSymbolAddress((void**)&Eh, g_Eh);

    constexpr int SMEM128 = 3 * (128 * 64 * 2 + 128 * 64 * 2);   // 96 KB
    constexpr int SMEM64  = 3 * (128 * 64 * 2 + 64 * 64 * 2);    // 72 KB
    cudaFuncSetAttribute(mma_gemm_kernel<1, 128>, cudaFuncAttributeMaxDynamicSharedMemorySize, SMEM128);
    cudaFuncSetAttribute(mma_gemm_kernel<2, 128>, cudaFuncAttributeMaxDynamicSharedMemorySize, SMEM128);
    cudaFuncSetAttribute(mma_gemm_kernel<3, 64>,  cudaFuncAttributeMaxDynamicSharedMemorySize, SMEM64);

    // 0: RoPE tables
    rope_tables_kernel<<<(MM * HALF_D + 255) / 256, 256>>>();
    // 1: x -> fp16
    cvt_x_kernel<<<(int)(((long)ROWS * DD / 4 + 255) / 256), 256>>>(x, xh);
    // 2: weights -> fp16
    dim3 gW((DD * DD / 4 + 255) / 256, 1, 3);
    cvt_w_kernel<<<gW, 256>>>(wq, wk, wv, wh);

    // 3: Merged QKV projection; epilogue emits Qh/Kh (RoPE) and VhT (transposed)
    dim3 gProj(3 * DD / 128, ROWS / 128, 1);
    mma_gemm_kernel<1, 128><<<gProj, 128, SMEM128>>>(xh, wh, nullptr, DD, 0, 0, 0, 0, 1.0f);

    // 4: scores -> exp(scores) fp16 + partial row sums (K=1024)
    dim3 gScore(MM / 128, MM / 128, BB);
    mma_gemm_kernel<2, 128><<<gScore, 128, SMEM128>>>(Qh, Kh, nullptr, DD, 0,
                                                      (long)MM * DD, (long)MM * DD,
                                                      0, 0.03125f);

    // 5: out = exp(S) @ V / rowsum  (K=2048, 128x64 tiles)   <- ncu capture
    dim3 gOut(DD / 64, MM / 128, BB);
    mma_gemm_kernel<3, 64><<<gOut, 128, SMEM64>>>(Eh, VhT, out, MM, DD,
                                                  (long)MM * MM, (long)DD * MM,
                                                  (long)MM * DD, 1.0f);
}

// round 12
// speedup vs baseline: 2.5333x; 1.0542x over previous
#include <cuda_runtime.h>
#include <cuda_fp16.h>
#include <math.h>
#include <stdint.h>

// Problem dims (fixed)
#define BB 8
#define MM 2048
#define DD 1024
#define HALF_D 512
#define ROWS 16384           // BB*MM

// ---------------------------------------------------------------------------
// Device-global scratch (allocation-free, graph-capture safe). Plain fp16.
// ---------------------------------------------------------------------------
__device__ __half g_xh[(size_t)ROWS * DD];        // x fp16
__device__ __half g_wh[(size_t)(3 * DD) * DD];    // [wq;wk;wv] fp16
__device__ __half g_Qh[(size_t)ROWS * DD];        // rotated Q fp16
__device__ __half g_Kh[(size_t)ROWS * DD];        // rotated K fp16
__device__ __half g_VhT[(size_t)BB * DD * MM];    // V^T fp16 (from proj epilogue)
__device__ __half g_Eh[(size_t)BB * MM * MM];     // exp(scores) fp16
__device__ float g_psum[(size_t)ROWS * 32];       // per-row exp partial sums
__device__ float2 g_cs[(size_t)MM * HALF_D];      // interleaved {cos, sin}

// ---------------------------------------------------------------------------
// PTX helpers (base-ISA: mma.sync / ldmatrix / cp.async)
// ---------------------------------------------------------------------------
__device__ __forceinline__ uint32_t smem_u32(const void* p) {
    uint32_t a;
    asm("{ .reg .u64 t; cvta.to.shared.u64 t, %1; cvt.u32.u64 %0, t; }" : "=r"(a) : "l"(p));
    return a;
}
__device__ __forceinline__ void mma16816(float* d, const uint32_t* a, const uint32_t* b) {
    asm volatile(
        "mma.sync.aligned.m16n8k16.row.col.f32.f16.f16.f32 "
        "{%0,%1,%2,%3}, {%4,%5,%6,%7}, {%8,%9}, {%0,%1,%2,%3};"
        : "+f"(d[0]), "+f"(d[1]), "+f"(d[2]), "+f"(d[3])
        : "r"(a[0]), "r"(a[1]), "r"(a[2]), "r"(a[3]), "r"(b[0]), "r"(b[1]));
}
__device__ __forceinline__ void ldsm4(uint32_t* r, uint32_t addr) {
    asm volatile("ldmatrix.sync.aligned.m8n8.x4.shared.b16 {%0,%1,%2,%3}, [%4];"
                 : "=r"(r[0]), "=r"(r[1]), "=r"(r[2]), "=r"(r[3]) : "r"(addr));
}
__device__ __forceinline__ void cpasync16(uint32_t dst, const void* src) {
    asm volatile("cp.async.cg.shared.global [%0], [%1], 16;" :: "r"(dst), "l"(src));
}
__device__ __forceinline__ void cp_commit() {
    asm volatile("cp.async.commit_group;" ::: "memory");
}
template <int N>
__device__ __forceinline__ void cp_wait() {
    asm volatile("cp.async.wait_group %0;" :: "n"(N) : "memory");
}

// ---------------------------------------------------------------------------
// RoPE tables (interleaved cos/sin)
// ---------------------------------------------------------------------------
__global__ void rope_tables_kernel() {
    int idx = blockIdx.x * blockDim.x + threadIdx.x;
    if (idx >= MM * HALF_D) return;
    int m = idx / HALF_D;
    int i = idx % HALF_D;
    double theta_d = pow(10000.0, -2.0 * ((double)i - 1.0) / (double)DD);
    float ang = (float)m * (float)theta_d;
    g_cs[idx] = make_float2(cosf(ang), sinf(ang));
}

// ---------------------------------------------------------------------------
// fp32 -> fp16 for x
// ---------------------------------------------------------------------------
__global__ void cvt_x_kernel(const float* __restrict__ src, __half* __restrict__ dst) {
    long idx = ((long)blockIdx.x * blockDim.x + threadIdx.x) * 4;
    if (idx >= (long)ROWS * DD) return;
    float4 v = *reinterpret_cast<const float4*>(src + idx);
    *reinterpret_cast<__half2*>(dst + idx)     = __floats2half2_rn(v.x, v.y);
    *reinterpret_cast<__half2*>(dst + idx + 2) = __floats2half2_rn(v.z, v.w);
}

// ---------------------------------------------------------------------------
// All three weights -> fp16 in one launch (z selects w)
// ---------------------------------------------------------------------------
__global__ void cvt_w_kernel(const float* __restrict__ wq, const float* __restrict__ wk,
                             const float* __restrict__ wv, __half* __restrict__ dst) {
    long idx = ((long)blockIdx.x * blockDim.x + threadIdx.x) * 4;
    if (idx >= (long)DD * DD) return;
    const float* src = blockIdx.z == 0 ? wq : (blockIdx.z == 1 ? wk : wv);
    float4 v = *reinterpret_cast<const float4*>(src + idx);
    __half* r = dst + (long)blockIdx.z * DD * DD + idx;
    *reinterpret_cast<__half2*>(r)     = __floats2half2_rn(v.x, v.y);
    *reinterpret_cast<__half2*>(r + 2) = __floats2half2_rn(v.z, v.w);
}

// ---------------------------------------------------------------------------
// mma.sync fp16 GEMM (NT, both operands K-major).
// CTA tile 128 x NTILE, BK=64, 3-stage cp.async, XOR swizzle, 4 warps (2Mx2N),
// register fragment double-buffering. All epilogues stage results through
// smem and issue coalesced 16B row-segment stores.
//   EPI=1 (NTILE=128): merged QKV projection epilogue
//       cols [0,2048): RoPE -> g_Qh / g_Kh
//       cols [2048,3072): transpose -> g_VhT
//   EPI=2 (NTILE=128): scores epilogue: e = expf(alpha*s) -> g_Eh,
//       deterministic per-(row, 64-col slab) partial sums -> g_psum
//   EPI=3 (NTILE=64): PV epilogue: scale rows by 1/rowsum(g_psum), fp32 out
// ---------------------------------------------------------------------------
template <int EPI, int NTILE>
__global__ void __launch_bounds__(128, NTILE == 64 ? 3 : 2) mma_gemm_kernel(
    const __half* __restrict__ A, const __half* __restrict__ B,
    float* __restrict__ C, int K, int ldc, long sA, long sB, long sC, float alpha)
{
    constexpr int NT = NTILE / 16;            // n8 tiles per warp (8 or 4)
    constexpr int TILE_A = 128 * 64 * 2;      // 16 KB
    constexpr int TILE_B = NTILE * 64 * 2;    // 16 or 8 KB
    constexpr int STAGE = TILE_A + TILE_B;

    extern __shared__ char smem[];
    const uint32_t sb = smem_u32(smem);
    const int tid = threadIdx.x;
    const int wid = tid >> 5, lane = tid & 31;
    const int wm = wid & 1;          // warp M index (x64 rows)
    const int wn = wid >> 1;         // warp N index (x NTILE/2 cols)

    const long row0 = (long)blockIdx.y * 128;
    const long col0 = (long)blockIdx.x * NTILE;
    const __half* Abase = A + blockIdx.z * sA + row0 * K;
    const __half* Bbase = B + blockIdx.z * sB + col0 * K;
    float* Cbase = C + blockIdx.z * sC;

    const int ldRow = tid >> 3;      // rows 0..15 (+16*i)
    const int ldC = tid & 7;         // 16B chunk within 128B row

    float acc[4][NT][4];
#pragma unroll
    for (int i = 0; i < 4; i++)
#pragma unroll
        for (int j = 0; j < NT; j++)
#pragma unroll
            for (int q = 0; q < 4; q++) acc[i][j][q] = 0.0f;

    const int nch = K >> 6;

    auto load_tile = [&](int ch, int buf) {
        const int kk = ch << 6;
        const uint32_t sbA = sb + buf * STAGE;
        const uint32_t sbB = sbA + TILE_A;
#pragma unroll
        for (int i = 0; i < 8; i++) {
            int row = ldRow + i * 16;
            uint32_t off = ((uint32_t)row * 8u + (uint32_t)(ldC ^ (row & 7))) * 16u;
            cpasync16(sbA + off, Abase + (long)row * K + kk + ldC * 8);
        }
#pragma unroll
        for (int i = 0; i < NTILE / 16; i++) {
            int row = ldRow + i * 16;
            uint32_t off = ((uint32_t)row * 8u + (uint32_t)(ldC ^ (row & 7))) * 16u;
            cpasync16(sbB + off, Bbase + (long)row * K + kk + ldC * 8);
        }
    };

    const int lrow = lane & 15;
    const int lcol = lane >> 4;

    load_tile(0, 0);
    cp_commit();
    load_tile(1, 1);
    cp_commit();

    for (int ch = 0; ch < nch; ch++) {
        if (ch + 2 < nch) {
            load_tile(ch + 2, (ch + 2) % 3);
            cp_commit();
            cp_wait<2>();
        } else if (ch + 1 < nch) {
            cp_wait<1>();
        } else {
            cp_wait<0>();
        }
        __syncthreads();

        const uint32_t sbA = sb + (ch % 3) * STAGE;
        const uint32_t sbB = sbA + TILE_A;

        uint32_t fa[2][4][4];
        uint32_t fb[2][NT][2];

        auto load_frags = [&](int ks, int pb) {
#pragma unroll
            for (int mt = 0; mt < 4; mt++) {
                int row = wm * 64 + mt * 16 + lrow;
                int c = 2 * ks + lcol;
                uint32_t addr = sbA + ((uint32_t)row * 8u + (uint32_t)(c ^ (row & 7))) * 16u;
                ldsm4(fa[pb][mt], addr);
            }
#pragma unroll
            for (int p = 0; p < NT / 2; p++) {
                int row = wn * (NTILE / 2) + p * 16 + lrow;
                int c = 2 * ks + lcol;
                uint32_t addr = sbB + ((uint32_t)row * 8u + (uint32_t)(c ^ (row & 7))) * 16u;
                uint32_t r[4];
                ldsm4(r, addr);
                fb[pb][2 * p][0] = r[0]; fb[pb][2 * p][1] = r[2];
                fb[pb][2 * p + 1][0] = r[1]; fb[pb][2 * p + 1][1] = r[3];
            }
        };

        load_frags(0, 0);
#pragma unroll
        for (int ks = 0; ks < 4; ks++) {             // 4 k16 steps in BK=64
            if (ks < 3) load_frags(ks + 1, (ks + 1) & 1);
#pragma unroll
            for (int mt = 0; mt < 4; mt++)
#pragma unroll
                for (int nt = 0; nt < NT; nt++)
                    mma16816(acc[mt][nt], fa[ks & 1][mt], fb[ks & 1][nt]);
        }
        __syncthreads();
    }

    // ---- epilogue (all paths: smem staging + coalesced stores) ----
    const int g = lane >> 2, tg = lane & 3;
    constexpr int RS = 136;                  // staging row stride (halfs), 16B-aligned

    if (EPI == 1) {
        __half* sv = reinterpret_cast<__half*>(smem);
        if (col0 < 2048) {
            // Q/K tile: RoPE in regs -> smem -> coalesced stores
            const int k0 = (int)col0 & 1023;
#pragma unroll
            for (int mt = 0; mt < 4; mt++) {
                int rl = wm * 64 + mt * 16 + g;
#pragma unroll
                for (int nt = 0; nt < NT; nt++) {
                    int cl = wn * 64 + nt * 8 + tg * 2;
                    int pidx = (k0 + cl) >> 1;
#pragma unroll
                    for (int h = 0; h < 2; h++) {
                        int m = (int)((row0 + rl + h * 8) & (MM - 1));
                        float2 cs = g_cs[(size_t)m * HALF_D + pidx];
                        float e = acc[mt][nt][2 * h], o = acc[mt][nt][2 * h + 1];
                        float re = e * cs.x + o * cs.y;
                        float ro = -e * cs.y + o * cs.x;
                        *reinterpret_cast<__half2*>(&sv[(rl + h * 8) * RS + cl]) =
                            __floats2half2_rn(re, ro);
                    }
                }
            }
            __syncthreads();
            __half* base = (col0 < 1024 ? g_Qh : g_Kh);
#pragma unroll
            for (int it = 0; it < 16; it++) {
                int row = it * 8 + wid * 2 + (lane >> 4);
                int cc = (lane & 15) * 8;
                *reinterpret_cast<uint4*>(base + (row0 + row) * (long)DD + k0 + cc) =
                    *reinterpret_cast<uint4*>(&sv[row * RS + cc]);
            }
        } else {
            // V tile: transpose through smem, coalesced fp16 stores along M
#pragma unroll
            for (int mt = 0; mt < 4; mt++)
#pragma unroll
                for (int nt = 0; nt < NT; nt++) {
                    int cl = wn * 64 + nt * 8 + tg * 2;
#pragma unroll
                    for (int h = 0; h < 2; h++) {
                        int rl = wm * 64 + mt * 16 + g + h * 8;
                        *reinterpret_cast<__half2*>(&sv[rl * RS + cl]) =
                            __floats2half2_rn(acc[mt][nt][2 * h], acc[mt][nt][2 * h + 1]);
                    }
                }
            __syncthreads();
            int b = (int)(row0 >> 11);
            int m0 = (int)(row0 & (MM - 1));
            int vcol = (int)col0 - 2048 + tid;     // one column per thread
            __half* dst = g_VhT + ((long)(b * DD + vcol)) * MM + m0;
#pragma unroll
            for (int c8 = 0; c8 < 16; c8++) {
                __half tmp[8];
#pragma unroll
                for (int j = 0; j < 8; j++) tmp[j] = sv[(c8 * 8 + j) * RS + tid];
                *reinterpret_cast<uint4*>(dst + c8 * 8) = *reinterpret_cast<uint4*>(tmp);
            }
        }
    } else if (EPI == 2) {
        // scores epilogue: e = expf(alpha*s) -> smem -> coalesced; psum
        __half* sv = reinterpret_cast<__half*>(smem);
        float rs[4][2];
#pragma unroll
        for (int mt = 0; mt < 4; mt++) { rs[mt][0] = 0.0f; rs[mt][1] = 0.0f; }
#pragma unroll
        for (int mt = 0; mt < 4; mt++) {
            int rl = wm * 64 + mt * 16 + g;
#pragma unroll
            for (int nt = 0; nt < NT; nt++) {
                int cl = wn * 64 + nt * 8 + tg * 2;
#pragma unroll
                for (int h = 0; h < 2; h++) {
                    float e0 = expf(alpha * acc[mt][nt][2 * h]);
                    float e1 = expf(alpha * acc[mt][nt][2 * h + 1]);
                    *reinterpret_cast<__half2*>(&sv[(rl + h * 8) * RS + cl]) =
                        __floats2half2_rn(e0, e1);
                    rs[mt][h] += e0 + e1;
                }
            }
        }
        // reduce across tg (lanes 0..3 within each row group)
#pragma unroll
        for (int mt = 0; mt < 4; mt++)
#pragma unroll
            for (int h = 0; h < 2; h++) {
                float v = rs[mt][h];
                v += __shfl_xor_sync(0xffffffffu, v, 1);
                v += __shfl_xor_sync(0xffffffffu, v, 2);
                rs[mt][h] = v;
            }
        if (tg == 0) {
#pragma unroll
            for (int mt = 0; mt < 4; mt++)
#pragma unroll
                for (int h = 0; h < 2; h++) {
                    long rr = row0 + wm * 64 + mt * 16 + g + h * 8;
                    g_psum[((long)blockIdx.z * MM + rr) * 32 + blockIdx.x * 2 + wn] = rs[mt][h];
                }
        }
        __syncthreads();
        __half* Eb = g_Eh + (long)blockIdx.z * MM * MM;
#pragma unroll
        for (int it = 0; it < 16; it++) {
            int row = it * 8 + wid * 2 + (lane >> 4);
            int cc = (lane & 15) * 8;
            *reinterpret_cast<uint4*>(Eb + (row0 + row) * MM + col0 + cc) =
                *reinterpret_cast<uint4*>(&sv[row * RS + cc]);
        }
    } else {
        // EPI == 3: PV epilogue — divide by row sums, fp32 staging
        constexpr int RSF = 68;              // fp32 staging stride, 16B-aligned
        float* svf = reinterpret_cast<float*>(smem);
        float* s_inv = reinterpret_cast<float*>(smem + 128 * RSF * 4);
        {
            const float4* pp = reinterpret_cast<const float4*>(
                g_psum + ((long)blockIdx.z * MM + row0 + tid) * 32);
            float s = 0.0f;
#pragma unroll
            for (int q = 0; q < 8; q++) {
                float4 v = pp[q];
                s += (v.x + v.y) + (v.z + v.w);
            }
            s_inv[tid] = 1.0f / s;
        }
        __syncthreads();
#pragma unroll
        for (int mt = 0; mt < 4; mt++) {
            int l0 = wm * 64 + mt * 16 + g;
            float inv0 = s_inv[l0];
            float inv1 = s_inv[l0 + 8];
#pragma unroll
            for (int nt = 0; nt < NT; nt++) {
                int cl = wn * (NTILE / 2) + nt * 8 + tg * 2;
                *reinterpret_cast<float2*>(&svf[l0 * RSF + cl]) =
                    make_float2(acc[mt][nt][0] * inv0, acc[mt][nt][1] * inv0);
                *reinterpret_cast<float2*>(&svf[(l0 + 8) * RSF + cl]) =
                    make_float2(acc[mt][nt][2] * inv1, acc[mt][nt][3] * inv1);
            }
        }
        __syncthreads();
#pragma unroll
        for (int it = 0; it < 16; it++) {
            int row = it * 8 + wid * 2 + (lane >> 4);
            int cc = (lane & 15) * 4;
            *reinterpret_cast<uint4*>(Cbase + (row0 + row) * ldc + col0 + cc) =
                *reinterpret_cast<uint4*>(&svf[row * RSF + cc]);
        }
    }
}

// ---------------------------------------------------------------------------
// Launch. 6 kernels: tables, cvt_x, cvt_w, proj, scores, PV.
// ---------------------------------------------------------------------------
extern "C" void kernel_launch(void* const* d_in, const int* in_sizes, int n_in,
                              void* d_out, int out_size) {
    (void)in_sizes; (void)n_in; (void)out_size;
    const float* x  = (const float*)d_in[0];
    const float* wq = (const float*)d_in[1];
    const float* wk = (const float*)d_in[2];
    const float* wv = (const float*)d_in[3];
    float* out = (float*)d_out;

    __half *xh, *wh, *Qh, *Kh, *VhT, *Eh;
    cudaGetSymbolAddress((void**)&xh, g_xh);
    cudaGetSymbolAddress((void**)&wh, g_wh);
    cudaGetSymbolAddress((void**)&Qh, g_Qh);
    cudaGetSymbolAddress((void**)&Kh, g_Kh);
    cudaGetSymbolAddress((void**)&VhT, g_VhT);
    cudaGetSymbolAddress((void**)&Eh, g_Eh);

    constexpr int SMEM128 = 3 * (128 * 64 * 2 + 128 * 64 * 2);   // 96 KB
    constexpr int SMEM64  = 3 * (128 * 64 * 2 + 64 * 64 * 2);    // 72 KB
    cudaFuncSetAttribute(mma_gemm_kernel<1, 128>, cudaFuncAttributeMaxDynamicSharedMemorySize, SMEM128);
    cudaFuncSetAttribute(mma_gemm_kernel<2, 128>, cudaFuncAttributeMaxDynamicSharedMemorySize, SMEM128);
    cudaFuncSetAttribute(mma_gemm_kernel<3, 64>,  cudaFuncAttributeMaxDynamicSharedMemorySize, SMEM64);

    // 0: RoPE tables
    rope_tables_kernel<<<(MM * HALF_D + 255) / 256, 256>>>();
    // 1: x -> fp16
    cvt_x_kernel<<<(int)(((long)ROWS * DD / 4 + 255) / 256), 256>>>(x, xh);
    // 2: weights -> fp16
    dim3 gW((DD * DD / 4 + 255) / 256, 1, 3);
    cvt_w_kernel<<<gW, 256>>>(wq, wk, wv, wh);

    // 3: Merged QKV projection; epilogue emits Qh/Kh (RoPE) and VhT (transposed)
    dim3 gProj(3 * DD / 128, ROWS / 128, 1);
    mma_gemm_kernel<1, 128><<<gProj, 128, SMEM128>>>(xh, wh, nullptr, DD, 0, 0, 0, 0, 1.0f);

    // 4: scores -> exp(scores) fp16 + partial row sums (K=1024)
    dim3 gScore(MM / 128, MM / 128, BB);
    mma_gemm_kernel<2, 128><<<gScore, 128, SMEM128>>>(Qh, Kh, nullptr, DD, 0,
                                                      (long)MM * DD, (long)MM * DD,
                                                      0, 0.03125f);

    // 5: out = exp(S) @ V / rowsum  (K=2048, 128x64 tiles)   <- ncu capture
    dim3 gOut(DD / 64, MM / 128, BB);
    mma_gemm_kernel<3, 64><<<gOut, 128, SMEM64>>>(Eh, VhT, out, MM, DD,
                                                  (long)MM * MM, (long)DD * MM,
                                                  (long)MM * DD, 1.0f);
}

// round 13
// speedup vs baseline: 2.5335x; 1.0001x over previous
#include <cuda_runtime.h>
#include <cuda_fp16.h>
#include <math.h>
#include <stdint.h>

// Problem dims (fixed)
#define BB 8
#define MM 2048
#define DD 1024
#define HALF_D 512
#define ROWS 16384           // BB*MM

// ---------------------------------------------------------------------------
// Device-global scratch (allocation-free, graph-capture safe). Plain fp16.
// ---------------------------------------------------------------------------
__device__ __half g_xh[(size_t)ROWS * DD];        // x fp16
__device__ __half g_wh[(size_t)(3 * DD) * DD];    // [wq;wk;wv] fp16
__device__ __half g_Qh[(size_t)ROWS * DD];        // rotated Q fp16
__device__ __half g_Kh[(size_t)ROWS * DD];        // rotated K fp16
__device__ __half g_VhT[(size_t)BB * DD * MM];    // V^T fp16 (from proj epilogue)
__device__ __half g_Eh[(size_t)BB * MM * MM];     // exp(scores) fp16
__device__ float g_psum[(size_t)ROWS * 32];       // per-row exp partial sums
__device__ float2 g_cs[(size_t)MM * HALF_D];      // interleaved {cos, sin}

// ---------------------------------------------------------------------------
// PTX helpers (base-ISA: mma.sync / ldmatrix / cp.async)
// ---------------------------------------------------------------------------
__device__ __forceinline__ uint32_t smem_u32(const void* p) {
    uint32_t a;
    asm("{ .reg .u64 t; cvta.to.shared.u64 t, %1; cvt.u32.u64 %0, t; }" : "=r"(a) : "l"(p));
    return a;
}
__device__ __forceinline__ void mma16816(float* d, const uint32_t* a, const uint32_t* b) {
    asm volatile(
        "mma.sync.aligned.m16n8k16.row.col.f32.f16.f16.f32 "
        "{%0,%1,%2,%3}, {%4,%5,%6,%7}, {%8,%9}, {%0,%1,%2,%3};"
        : "+f"(d[0]), "+f"(d[1]), "+f"(d[2]), "+f"(d[3])
        : "r"(a[0]), "r"(a[1]), "r"(a[2]), "r"(a[3]), "r"(b[0]), "r"(b[1]));
}
__device__ __forceinline__ void ldsm4(uint32_t* r, uint32_t addr) {
    asm volatile("ldmatrix.sync.aligned.m8n8.x4.shared.b16 {%0,%1,%2,%3}, [%4];"
                 : "=r"(r[0]), "=r"(r[1]), "=r"(r[2]), "=r"(r[3]) : "r"(addr));
}
__device__ __forceinline__ void cpasync16(uint32_t dst, const void* src) {
    asm volatile("cp.async.cg.shared.global [%0], [%1], 16;" :: "r"(dst), "l"(src));
}
__device__ __forceinline__ void cp_commit() {
    asm volatile("cp.async.commit_group;" ::: "memory");
}
template <int N>
__device__ __forceinline__ void cp_wait() {
    asm volatile("cp.async.wait_group %0;" :: "n"(N) : "memory");
}

// ---------------------------------------------------------------------------
// Prep kernel: RoPE tables + x->fp16 + weights->fp16, one launch.
// Block ranges: [0,4096) tables | [4096,20480) cvt_x | [20480,23552) cvt_w
// ---------------------------------------------------------------------------
__global__ void prep_kernel(const float* __restrict__ x,
                            const float* __restrict__ wq,
                            const float* __restrict__ wk,
                            const float* __restrict__ wv) {
    int b = blockIdx.x;
    int t = threadIdx.x;
    if (b < 4096) {
        int idx = b * 256 + t;                 // MM*HALF_D = 1048576
        int m = idx / HALF_D;
        int i = idx % HALF_D;
        double theta_d = pow(10000.0, -2.0 * ((double)i - 1.0) / (double)DD);
        float ang = (float)m * (float)theta_d;
        g_cs[idx] = make_float2(cosf(ang), sinf(ang));
    } else if (b < 20480) {
        long idx = ((long)(b - 4096) * 256 + t) * 4;   // ROWS*DD = 16777216
        float4 v = *reinterpret_cast<const float4*>(x + idx);
        *reinterpret_cast<__half2*>(g_xh + idx)     = __floats2half2_rn(v.x, v.y);
        *reinterpret_cast<__half2*>(g_xh + idx + 2) = __floats2half2_rn(v.z, v.w);
    } else {
        int j = b - 20480;                     // 3 * 1024 blocks
        int w = j >> 10;
        long idx = ((long)(j & 1023) * 256 + t) * 4;   // DD*DD/4 quads
        const float* src = w == 0 ? wq : (w == 1 ? wk : wv);
        float4 v = *reinterpret_cast<const float4*>(src + idx);
        __half* r = g_wh + (long)w * DD * DD + idx;
        *reinterpret_cast<__half2*>(r)     = __floats2half2_rn(v.x, v.y);
        *reinterpret_cast<__half2*>(r + 2) = __floats2half2_rn(v.z, v.w);
    }
}

// ---------------------------------------------------------------------------
// Persistent mma.sync fp16 GEMM (NT, both operands K-major).
// Grid-stride loop over output tiles; CTA tile 128 x NTILE, BK=64, 3-stage
// cp.async, XOR swizzle, 4 warps (2Mx2N), register fragment double-buffering.
// Epilogues stage through smem, coalesced 16B stores.
//   EPI=1: merged QKV projection (RoPE Q/K, transpose V)
//   EPI=2: scores: exp(alpha*s) -> g_Eh + psum
//   EPI=3: PV: scale by 1/rowsum -> fp32 out
// ---------------------------------------------------------------------------
template <int EPI, int NTILE>
__global__ void __launch_bounds__(128, NTILE == 64 ? 3 : 2) mma_gemm_kernel(
    const __half* __restrict__ A, const __half* __restrict__ B,
    float* __restrict__ C, int K, int ldc, long sA, long sB, long sC, float alpha,
    int tX, int tXY, int ntiles)
{
    constexpr int NT = NTILE / 16;            // n8 tiles per warp (8 or 4)
    constexpr int TILE_A = 128 * 64 * 2;      // 16 KB
    constexpr int TILE_B = NTILE * 64 * 2;    // 16 or 8 KB
    constexpr int STAGE = TILE_A + TILE_B;
    constexpr int RS = 136;                   // epi staging stride (halfs)

    extern __shared__ char smem[];
    const uint32_t sb = smem_u32(smem);
    const int tid = threadIdx.x;
    const int wid = tid >> 5, lane = tid & 31;
    const int wm = wid & 1;
    const int wn = wid >> 1;
    const int ldRow = tid >> 3;
    const int ldC = tid & 7;
    const int lrow = lane & 15;
    const int lcol = lane >> 4;
    const int g = lane >> 2, tg = lane & 3;
    const int nch = K >> 6;

    for (int tidx = blockIdx.x; tidx < ntiles; tidx += gridDim.x) {
        const int bz = tidx / tXY;
        const int rem = tidx - bz * tXY;
        const int by = rem / tX;
        const int bx = rem - by * tX;

        const long row0 = (long)by * 128;
        const long col0 = (long)bx * NTILE;
        const __half* Abase = A + bz * sA + row0 * K;
        const __half* Bbase = B + bz * sB + col0 * K;
        float* Cbase = C + bz * sC;

        float acc[4][NT][4];
#pragma unroll
        for (int i = 0; i < 4; i++)
#pragma unroll
            for (int j = 0; j < NT; j++)
#pragma unroll
                for (int q = 0; q < 4; q++) acc[i][j][q] = 0.0f;

        auto load_tile = [&](int ch, int buf) {
            const int kk = ch << 6;
            const uint32_t sbA = sb + buf * STAGE;
            const uint32_t sbB = sbA + TILE_A;
#pragma unroll
            for (int i = 0; i < 8; i++) {
                int row = ldRow + i * 16;
                uint32_t off = ((uint32_t)row * 8u + (uint32_t)(ldC ^ (row & 7))) * 16u;
                cpasync16(sbA + off, Abase + (long)row * K + kk + ldC * 8);
            }
#pragma unroll
            for (int i = 0; i < NTILE / 16; i++) {
                int row = ldRow + i * 16;
                uint32_t off = ((uint32_t)row * 8u + (uint32_t)(ldC ^ (row & 7))) * 16u;
                cpasync16(sbB + off, Bbase + (long)row * K + kk + ldC * 8);
            }
        };

        load_tile(0, 0);
        cp_commit();
        load_tile(1, 1);
        cp_commit();

        for (int ch = 0; ch < nch; ch++) {
            if (ch + 2 < nch) {
                load_tile(ch + 2, (ch + 2) % 3);
                cp_commit();
                cp_wait<2>();
            } else if (ch + 1 < nch) {
                cp_wait<1>();
            } else {
                cp_wait<0>();
            }
            __syncthreads();

            const uint32_t sbA = sb + (ch % 3) * STAGE;
            const uint32_t sbB = sbA + TILE_A;

            uint32_t fa[2][4][4];
            uint32_t fb[2][NT][2];

            auto load_frags = [&](int ks, int pb) {
#pragma unroll
                for (int mt = 0; mt < 4; mt++) {
                    int row = wm * 64 + mt * 16 + lrow;
                    int c = 2 * ks + lcol;
                    uint32_t addr = sbA + ((uint32_t)row * 8u + (uint32_t)(c ^ (row & 7))) * 16u;
                    ldsm4(fa[pb][mt], addr);
                }
#pragma unroll
                for (int p = 0; p < NT / 2; p++) {
                    int row = wn * (NTILE / 2) + p * 16 + lrow;
                    int c = 2 * ks + lcol;
                    uint32_t addr = sbB + ((uint32_t)row * 8u + (uint32_t)(c ^ (row & 7))) * 16u;
                    uint32_t r[4];
                    ldsm4(r, addr);
                    fb[pb][2 * p][0] = r[0]; fb[pb][2 * p][1] = r[2];
                    fb[pb][2 * p + 1][0] = r[1]; fb[pb][2 * p + 1][1] = r[3];
                }
            };

            load_frags(0, 0);
#pragma unroll
            for (int ks = 0; ks < 4; ks++) {
                if (ks < 3) load_frags(ks + 1, (ks + 1) & 1);
#pragma unroll
                for (int mt = 0; mt < 4; mt++)
#pragma unroll
                    for (int nt = 0; nt < NT; nt++)
                        mma16816(acc[mt][nt], fa[ks & 1][mt], fb[ks & 1][nt]);
            }
            __syncthreads();
        }

        // ---- epilogue (smem staging + coalesced stores) ----
        if (EPI == 1) {
            __half* sv = reinterpret_cast<__half*>(smem);
            if (col0 < 2048) {
                const int k0 = (int)col0 & 1023;
#pragma unroll
                for (int mt = 0; mt < 4; mt++) {
                    int rl = wm * 64 + mt * 16 + g;
#pragma unroll
                    for (int nt = 0; nt < NT; nt++) {
                        int cl = wn * 64 + nt * 8 + tg * 2;
                        int pidx = (k0 + cl) >> 1;
#pragma unroll
                        for (int h = 0; h < 2; h++) {
                            int m = (int)((row0 + rl + h * 8) & (MM - 1));
                            float2 cs = g_cs[(size_t)m * HALF_D + pidx];
                            float e = acc[mt][nt][2 * h], o = acc[mt][nt][2 * h + 1];
                            float re = e * cs.x + o * cs.y;
                            float ro = -e * cs.y + o * cs.x;
                            *reinterpret_cast<__half2*>(&sv[(rl + h * 8) * RS + cl]) =
                                __floats2half2_rn(re, ro);
                        }
                    }
                }
                __syncthreads();
                __half* base = (col0 < 1024 ? g_Qh : g_Kh);
#pragma unroll
                for (int it = 0; it < 16; it++) {
                    int row = it * 8 + wid * 2 + (lane >> 4);
                    int cc = (lane & 15) * 8;
                    *reinterpret_cast<uint4*>(base + (row0 + row) * (long)DD + k0 + cc) =
                        *reinterpret_cast<uint4*>(&sv[row * RS + cc]);
                }
            } else {
#pragma unroll
                for (int mt = 0; mt < 4; mt++)
#pragma unroll
                    for (int nt = 0; nt < NT; nt++) {
                        int cl = wn * 64 + nt * 8 + tg * 2;
#pragma unroll
                        for (int h = 0; h < 2; h++) {
                            int rl = wm * 64 + mt * 16 + g + h * 8;
                            *reinterpret_cast<__half2*>(&sv[rl * RS + cl]) =
                                __floats2half2_rn(acc[mt][nt][2 * h], acc[mt][nt][2 * h + 1]);
                        }
                    }
                __syncthreads();
                int b = (int)(row0 >> 11);
                int m0 = (int)(row0 & (MM - 1));
                int vcol = (int)col0 - 2048 + tid;
                __half* dst = g_VhT + ((long)(b * DD + vcol)) * MM + m0;
#pragma unroll
                for (int c8 = 0; c8 < 16; c8++) {
                    __half tmp[8];
#pragma unroll
                    for (int j = 0; j < 8; j++) tmp[j] = sv[(c8 * 8 + j) * RS + tid];
                    *reinterpret_cast<uint4*>(dst + c8 * 8) = *reinterpret_cast<uint4*>(tmp);
                }
            }
        } else if (EPI == 2) {
            __half* sv = reinterpret_cast<__half*>(smem);
            float rs[4][2];
#pragma unroll
            for (int mt = 0; mt < 4; mt++) { rs[mt][0] = 0.0f; rs[mt][1] = 0.0f; }
#pragma unroll
            for (int mt = 0; mt < 4; mt++) {
                int rl = wm * 64 + mt * 16 + g;
#pragma unroll
                for (int nt = 0; nt < NT; nt++) {
                    int cl = wn * 64 + nt * 8 + tg * 2;
#pragma unroll
                    for (int h = 0; h < 2; h++) {
                        float e0 = expf(alpha * acc[mt][nt][2 * h]);
                        float e1 = expf(alpha * acc[mt][nt][2 * h + 1]);
                        *reinterpret_cast<__half2*>(&sv[(rl + h * 8) * RS + cl]) =
                            __floats2half2_rn(e0, e1);
                        rs[mt][h] += e0 + e1;
                    }
                }
            }
#pragma unroll
            for (int mt = 0; mt < 4; mt++)
#pragma unroll
                for (int h = 0; h < 2; h++) {
                    float v = rs[mt][h];
                    v += __shfl_xor_sync(0xffffffffu, v, 1);
                    v += __shfl_xor_sync(0xffffffffu, v, 2);
                    rs[mt][h] = v;
                }
            if (tg == 0) {
#pragma unroll
                for (int mt = 0; mt < 4; mt++)
#pragma unroll
                    for (int h = 0; h < 2; h++) {
                        long rr = row0 + wm * 64 + mt * 16 + g + h * 8;
                        g_psum[((long)bz * MM + rr) * 32 + bx * 2 + wn] = rs[mt][h];
                    }
            }
            __syncthreads();
            __half* Eb = g_Eh + (long)bz * MM * MM;
#pragma unroll
            for (int it = 0; it < 16; it++) {
                int row = it * 8 + wid * 2 + (lane >> 4);
                int cc = (lane & 15) * 8;
                *reinterpret_cast<uint4*>(Eb + (row0 + row) * MM + col0 + cc) =
                    *reinterpret_cast<uint4*>(&sv[row * RS + cc]);
            }
        } else {
            constexpr int RSF = 68;
            float* svf = reinterpret_cast<float*>(smem);
            float* s_inv = reinterpret_cast<float*>(smem + 128 * RSF * 4);
            {
                const float4* pp = reinterpret_cast<const float4*>(
                    g_psum + ((long)bz * MM + row0 + tid) * 32);
                float s = 0.0f;
#pragma unroll
                for (int q = 0; q < 8; q++) {
                    float4 v = pp[q];
                    s += (v.x + v.y) + (v.z + v.w);
                }
                s_inv[tid] = 1.0f / s;
            }
            __syncthreads();
#pragma unroll
            for (int mt = 0; mt < 4; mt++) {
                int l0 = wm * 64 + mt * 16 + g;
                float inv0 = s_inv[l0];
                float inv1 = s_inv[l0 + 8];
#pragma unroll
                for (int nt = 0; nt < NT; nt++) {
                    int cl = wn * (NTILE / 2) + nt * 8 + tg * 2;
                    *reinterpret_cast<float2*>(&svf[l0 * RSF + cl]) =
                        make_float2(acc[mt][nt][0] * inv0, acc[mt][nt][1] * inv0);
                    *reinterpret_cast<float2*>(&svf[(l0 + 8) * RSF + cl]) =
                        make_float2(acc[mt][nt][2] * inv1, acc[mt][nt][3] * inv1);
                }
            }
            __syncthreads();
#pragma unroll
            for (int it = 0; it < 16; it++) {
                int row = it * 8 + wid * 2 + (lane >> 4);
                int cc = (lane & 15) * 4;
                *reinterpret_cast<uint4*>(Cbase + (row0 + row) * ldc + col0 + cc) =
                    *reinterpret_cast<uint4*>(&svf[row * RSF + cc]);
            }
        }
        __syncthreads();   // protect staging smem before next tile's cp.async
    }
}

// ---------------------------------------------------------------------------
// Launch. 4 kernels: prep, proj, scores, PV. Persistent grids.
// ---------------------------------------------------------------------------
extern "C" void kernel_launch(void* const* d_in, const int* in_sizes, int n_in,
                              void* d_out, int out_size) {
    (void)in_sizes; (void)n_in; (void)out_size;
    const float* x  = (const float*)d_in[0];
    const float* wq = (const float*)d_in[1];
    const float* wk = (const float*)d_in[2];
    const float* wv = (const float*)d_in[3];
    float* out = (float*)d_out;

    __half *xh, *wh, *Qh, *Kh, *VhT, *Eh;
    cudaGetSymbolAddress((void**)&xh, g_xh);
    cudaGetSymbolAddress((void**)&wh, g_wh);
    cudaGetSymbolAddress((void**)&Qh, g_Qh);
    cudaGetSymbolAddress((void**)&Kh, g_Kh);
    cudaGetSymbolAddress((void**)&VhT, g_VhT);
    cudaGetSymbolAddress((void**)&Eh, g_Eh);

    constexpr int SMEM128 = 3 * (128 * 64 * 2 + 128 * 64 * 2);   // 96 KB
    constexpr int SMEM64  = 3 * (128 * 64 * 2 + 64 * 64 * 2);    // 72 KB
    cudaFuncSetAttribute(mma_gemm_kernel<1, 128>, cudaFuncAttributeMaxDynamicSharedMemorySize, SMEM128);
    cudaFuncSetAttribute(mma_gemm_kernel<2, 128>, cudaFuncAttributeMaxDynamicSharedMemorySize, SMEM128);
    cudaFuncSetAttribute(mma_gemm_kernel<3, 64>,  cudaFuncAttributeMaxDynamicSharedMemorySize, SMEM64);

    // 0: prep (tables + cvt_x + cvt_w)
    prep_kernel<<<23552, 256>>>(x, wq, wk, wv);

    // 1: Merged QKV projection (persistent, 24x128 tiles)
    mma_gemm_kernel<1, 128><<<296, 128, SMEM128>>>(xh, wh, nullptr, DD, 0,
                                                   0, 0, 0, 1.0f,
                                                   24, 24 * 128, 3072);

    // 2: scores -> exp fp16 + psum (persistent, 16x16x8 tiles)
    mma_gemm_kernel<2, 128><<<296, 128, SMEM128>>>(Qh, Kh, nullptr, DD, 0,
                                                   (long)MM * DD, (long)MM * DD, 0,
                                                   0.03125f,
                                                   16, 16 * 16, 2048);

    // 3: out = exp(S) @ V / rowsum (persistent, 16x16x8 tiles)
    mma_gemm_kernel<3, 64><<<444, 128, SMEM64>>>(Eh, VhT, out, MM, DD,
                                                 (long)MM * MM, (long)DD * MM,
                                                 (long)MM * DD, 1.0f,
                                                 16, 16 * 16, 2048);
}

// round 14
// speedup vs baseline: 2.5822x; 1.0192x over previous
#include <cuda_runtime.h>
#include <cuda_fp16.h>
#include <math.h>
#include <stdint.h>

// Problem dims (fixed)
#define BB 8
#define MM 2048
#define DD 1024
#define HALF_D 512
#define ROWS 16384           // BB*MM

// ---------------------------------------------------------------------------
// Device-global scratch (allocation-free, graph-capture safe). Plain fp16.
// ---------------------------------------------------------------------------
__device__ __half g_xh[(size_t)ROWS * DD];        // x fp16
__device__ __half g_wh[(size_t)(3 * DD) * DD];    // [wq;wk;wv] fp16
__device__ __half g_Qh[(size_t)ROWS * DD];        // rotated Q fp16
__device__ __half g_Kh[(size_t)ROWS * DD];        // rotated K fp16
__device__ __half g_VhT[(size_t)BB * DD * MM];    // V^T fp16 (from proj epilogue)
__device__ __half g_Eh[(size_t)BB * MM * MM];     // exp(scores) fp16
__device__ float g_psum[(size_t)ROWS * 32];       // per-row exp partial sums
__device__ float2 g_cs[(size_t)MM * HALF_D];      // interleaved {cos, sin}

// ---------------------------------------------------------------------------
// PTX helpers (base-ISA: mma.sync / ldmatrix / cp.async)
// ---------------------------------------------------------------------------
__device__ __forceinline__ uint32_t smem_u32(const void* p) {
    uint32_t a;
    asm("{ .reg .u64 t; cvta.to.shared.u64 t, %1; cvt.u32.u64 %0, t; }" : "=r"(a) : "l"(p));
    return a;
}
__device__ __forceinline__ void mma16816(float* d, const uint32_t* a, const uint32_t* b) {
    asm volatile(
        "mma.sync.aligned.m16n8k16.row.col.f32.f16.f16.f32 "
        "{%0,%1,%2,%3}, {%4,%5,%6,%7}, {%8,%9}, {%0,%1,%2,%3};"
        : "+f"(d[0]), "+f"(d[1]), "+f"(d[2]), "+f"(d[3])
        : "r"(a[0]), "r"(a[1]), "r"(a[2]), "r"(a[3]), "r"(b[0]), "r"(b[1]));
}
__device__ __forceinline__ void ldsm4(uint32_t* r, uint32_t addr) {
    asm volatile("ldmatrix.sync.aligned.m8n8.x4.shared.b16 {%0,%1,%2,%3}, [%4];"
                 : "=r"(r[0]), "=r"(r[1]), "=r"(r[2]), "=r"(r[3]) : "r"(addr));
}
__device__ __forceinline__ void cpasync16(uint32_t dst, const void* src) {
    asm volatile("cp.async.cg.shared.global [%0], [%1], 16;" :: "r"(dst), "l"(src));
}
__device__ __forceinline__ void cp_commit() {
    asm volatile("cp.async.commit_group;" ::: "memory");
}
template <int N>
__device__ __forceinline__ void cp_wait() {
    asm volatile("cp.async.wait_group %0;" :: "n"(N) : "memory");
}

// ---------------------------------------------------------------------------
// Prep kernel: RoPE tables + x->fp16 + weights->fp16, one launch.
// ---------------------------------------------------------------------------
__global__ void prep_kernel(const float* __restrict__ x,
                            const float* __restrict__ wq,
                            const float* __restrict__ wk,
                            const float* __restrict__ wv) {
    int b = blockIdx.x;
    int t = threadIdx.x;
    if (b < 4096) {
        int idx = b * 256 + t;
        int m = idx / HALF_D;
        int i = idx % HALF_D;
        double theta_d = pow(10000.0, -2.0 * ((double)i - 1.0) / (double)DD);
        float ang = (float)m * (float)theta_d;
        g_cs[idx] = make_float2(cosf(ang), sinf(ang));
    } else if (b < 20480) {
        long idx = ((long)(b - 4096) * 256 + t) * 4;
        float4 v = *reinterpret_cast<const float4*>(x + idx);
        *reinterpret_cast<__half2*>(g_xh + idx)     = __floats2half2_rn(v.x, v.y);
        *reinterpret_cast<__half2*>(g_xh + idx + 2) = __floats2half2_rn(v.z, v.w);
    } else {
        int j = b - 20480;
        int w = j >> 10;
        long idx = ((long)(j & 1023) * 256 + t) * 4;
        const float* src = w == 0 ? wq : (w == 1 ? wk : wv);
        float4 v = *reinterpret_cast<const float4*>(src + idx);
        __half* r = g_wh + (long)w * DD * DD + idx;
        *reinterpret_cast<__half2*>(r)     = __floats2half2_rn(v.x, v.y);
        *reinterpret_cast<__half2*>(r + 2) = __floats2half2_rn(v.z, v.w);
    }
}

// ---------------------------------------------------------------------------
// Persistent mma.sync fp16 GEMM, 128x128 CTA tiles, BK=64, 2-stage cp.async
// pipeline made CONTINUOUS across tiles (chunks of tile t+1 prefetch during
// the last chunks of tile t; epilogue overlaps those loads). Dedicated smem
// staging region for all epilogues (coalesced 16B stores).
//   EPI=1: merged QKV projection (RoPE Q/K, transpose V)
//   EPI=2: scores: exp(alpha*s) -> g_Eh + psum
//   EPI=3: PV: scale by 1/rowsum -> fp32 out (two 64-col halves)
// ---------------------------------------------------------------------------
#define STAGEB 32768                       // one pipeline stage (A+B), bytes
#define EPIOFF (2 * STAGEB)                // staging region offset
#define GSMEM  (EPIOFF + 34816 + 512)      // total dynamic smem

template <int EPI>
__global__ void __launch_bounds__(128, 2) mma_gemm_kernel(
    const __half* __restrict__ A, const __half* __restrict__ B,
    float* __restrict__ C, int K, int ldc, long sA, long sB, long sC, float alpha,
    int tX, int tXY, int ntiles)
{
    constexpr int NT = 8;
    constexpr int TILE_A = 128 * 64 * 2;   // 16 KB
    constexpr int RS = 136;                // epi staging stride (halfs)

    extern __shared__ char smem[];
    const uint32_t sb = smem_u32(smem);
    const int tid = threadIdx.x;
    const int wid = tid >> 5, lane = tid & 31;
    const int wm = wid & 1;
    const int wn = wid >> 1;
    const int ldRow = tid >> 3;
    const int ldC = tid & 7;
    const int lrow = lane & 15;
    const int lcol = lane >> 4;
    const int g = lane >> 2, tg = lane & 3;
    const int nch = K >> 6;

    auto bases = [&](int t, const __half*& Ab, const __half*& Bb) {
        int bz = t / tXY;
        int rem = t - bz * tXY;
        int by = rem / tX;
        int bx = rem - by * tX;
        Ab = A + bz * sA + (long)by * 128 * K;
        Bb = B + bz * sB + (long)bx * 128 * K;
    };

    auto issue = [&](const __half* Ab, const __half* Bb, int ch, int buf) {
        const int kk = ch << 6;
        const uint32_t sbA = sb + buf * STAGEB;
        const uint32_t sbB = sbA + TILE_A;
#pragma unroll
        for (int i = 0; i < 8; i++) {
            int row = ldRow + i * 16;
            uint32_t off = ((uint32_t)row * 8u + (uint32_t)(ldC ^ (row & 7))) * 16u;
            cpasync16(sbA + off, Ab + (long)row * K + kk + ldC * 8);
            cpasync16(sbB + off, Bb + (long)row * K + kk + ldC * 8);
        }
        cp_commit();
    };

    const __half *curA = nullptr, *curB = nullptr, *nxtA = nullptr, *nxtB = nullptr;
    if (blockIdx.x < (unsigned)ntiles) {
        bases(blockIdx.x, curA, curB);
        issue(curA, curB, 0, 0);
        issue(curA, curB, 1, 1);
    }

    for (int tidx = blockIdx.x; tidx < ntiles; tidx += gridDim.x) {
        const int bz = tidx / tXY;
        const int rem = tidx - bz * tXY;
        const int by = rem / tX;
        const int bx = rem - by * tX;
        const long row0 = (long)by * 128;
        const long col0 = (long)bx * 128;
        float* Cbase = C + bz * sC;

        const int nt2 = tidx + gridDim.x;
        const bool hasNext = nt2 < ntiles;
        if (hasNext) bases(nt2, nxtA, nxtB);

        float acc[4][NT][4];
#pragma unroll
        for (int i = 0; i < 4; i++)
#pragma unroll
            for (int j = 0; j < NT; j++)
#pragma unroll
                for (int q = 0; q < 4; q++) acc[i][j][q] = 0.0f;

        for (int ch = 0; ch < nch; ch++) {
            if (!hasNext && ch == nch - 1) cp_wait<0>(); else cp_wait<1>();
            __syncthreads();

            const uint32_t sbA = sb + (ch & 1) * STAGEB;
            const uint32_t sbB = sbA + TILE_A;

            uint32_t fa[2][4][4];
            uint32_t fb[2][NT][2];

            auto load_frags = [&](int ks, int pb) {
#pragma unroll
                for (int mt = 0; mt < 4; mt++) {
                    int row = wm * 64 + mt * 16 + lrow;
                    int c = 2 * ks + lcol;
                    uint32_t addr = sbA + ((uint32_t)row * 8u + (uint32_t)(c ^ (row & 7))) * 16u;
                    ldsm4(fa[pb][mt], addr);
                }
#pragma unroll
                for (int p = 0; p < NT / 2; p++) {
                    int row = wn * 64 + p * 16 + lrow;
                    int c = 2 * ks + lcol;
                    uint32_t addr = sbB + ((uint32_t)row * 8u + (uint32_t)(c ^ (row & 7))) * 16u;
                    uint32_t r[4];
                    ldsm4(r, addr);
                    fb[pb][2 * p][0] = r[0]; fb[pb][2 * p][1] = r[2];
                    fb[pb][2 * p + 1][0] = r[1]; fb[pb][2 * p + 1][1] = r[3];
                }
            };

            load_frags(0, 0);
#pragma unroll
            for (int ks = 0; ks < 4; ks++) {
                if (ks < 3) load_frags(ks + 1, (ks + 1) & 1);
#pragma unroll
                for (int mt = 0; mt < 4; mt++)
#pragma unroll
                    for (int nt = 0; nt < NT; nt++)
                        mma16816(acc[mt][nt], fa[ks & 1][mt], fb[ks & 1][nt]);
            }
            __syncthreads();

            // continuous cross-tile prefetch
            int j = ch + 2;
            if (j < nch) issue(curA, curB, j, j & 1);
            else if (hasNext && j - nch < 2) issue(nxtA, nxtB, j - nch, j & 1);
        }

        // ---- epilogue (dedicated staging region; overlaps next-tile loads) --
        if (EPI == 1) {
            __half* sv = reinterpret_cast<__half*>(smem + EPIOFF);
            if (col0 < 2048) {
                const int k0 = (int)col0 & 1023;
#pragma unroll
                for (int mt = 0; mt < 4; mt++) {
                    int rl = wm * 64 + mt * 16 + g;
#pragma unroll
                    for (int nt = 0; nt < NT; nt++) {
                        int cl = wn * 64 + nt * 8 + tg * 2;
                        int pidx = (k0 + cl) >> 1;
#pragma unroll
                        for (int h = 0; h < 2; h++) {
                            int m = (int)((row0 + rl + h * 8) & (MM - 1));
                            float2 cs = g_cs[(size_t)m * HALF_D + pidx];
                            float e = acc[mt][nt][2 * h], o = acc[mt][nt][2 * h + 1];
                            float re = e * cs.x + o * cs.y;
                            float ro = -e * cs.y + o * cs.x;
                            *reinterpret_cast<__half2*>(&sv[(rl + h * 8) * RS + cl]) =
                                __floats2half2_rn(re, ro);
                        }
                    }
                }
                __syncthreads();
                __half* base = (col0 < 1024 ? g_Qh : g_Kh);
#pragma unroll
                for (int it = 0; it < 16; it++) {
                    int row = it * 8 + wid * 2 + (lane >> 4);
                    int cc = (lane & 15) * 8;
                    *reinterpret_cast<uint4*>(base + (row0 + row) * (long)DD + k0 + cc) =
                        *reinterpret_cast<uint4*>(&sv[row * RS + cc]);
                }
            } else {
#pragma unroll
                for (int mt = 0; mt < 4; mt++)
#pragma unroll
                    for (int nt = 0; nt < NT; nt++) {
                        int cl = wn * 64 + nt * 8 + tg * 2;
#pragma unroll
                        for (int h = 0; h < 2; h++) {
                            int rl = wm * 64 + mt * 16 + g + h * 8;
                            *reinterpret_cast<__half2*>(&sv[rl * RS + cl]) =
                                __floats2half2_rn(acc[mt][nt][2 * h], acc[mt][nt][2 * h + 1]);
                        }
                    }
                __syncthreads();
                int b = (int)(row0 >> 11);
                int m0 = (int)(row0 & (MM - 1));
                int vcol = (int)col0 - 2048 + tid;
                __half* dst = g_VhT + ((long)(b * DD + vcol)) * MM + m0;
#pragma unroll
                for (int c8 = 0; c8 < 16; c8++) {
                    __half tmp[8];
#pragma unroll
                    for (int jj = 0; jj < 8; jj++) tmp[jj] = sv[(c8 * 8 + jj) * RS + tid];
                    *reinterpret_cast<uint4*>(dst + c8 * 8) = *reinterpret_cast<uint4*>(tmp);
                }
            }
        } else if (EPI == 2) {
            __half* sv = reinterpret_cast<__half*>(smem + EPIOFF);
            float rs[4][2];
#pragma unroll
            for (int mt = 0; mt < 4; mt++) { rs[mt][0] = 0.0f; rs[mt][1] = 0.0f; }
#pragma unroll
            for (int mt = 0; mt < 4; mt++) {
                int rl = wm * 64 + mt * 16 + g;
#pragma unroll
                for (int nt = 0; nt < NT; nt++) {
                    int cl = wn * 64 + nt * 8 + tg * 2;
#pragma unroll
                    for (int h = 0; h < 2; h++) {
                        float e0 = expf(alpha * acc[mt][nt][2 * h]);
                        float e1 = expf(alpha * acc[mt][nt][2 * h + 1]);
                        *reinterpret_cast<__half2*>(&sv[(rl + h * 8) * RS + cl]) =
                            __floats2half2_rn(e0, e1);
                        rs[mt][h] += e0 + e1;
                    }
                }
            }
#pragma unroll
            for (int mt = 0; mt < 4; mt++)
#pragma unroll
                for (int h = 0; h < 2; h++) {
                    float v = rs[mt][h];
                    v += __shfl_xor_sync(0xffffffffu, v, 1);
                    v += __shfl_xor_sync(0xffffffffu, v, 2);
                    rs[mt][h] = v;
                }
            if (tg == 0) {
#pragma unroll
                for (int mt = 0; mt < 4; mt++)
#pragma unroll
                    for (int h = 0; h < 2; h++) {
                        long rr = row0 + wm * 64 + mt * 16 + g + h * 8;
                        g_psum[((long)bz * MM + rr) * 32 + bx * 2 + wn] = rs[mt][h];
                    }
            }
            __syncthreads();
            __half* Eb = g_Eh + (long)bz * MM * MM;
#pragma unroll
            for (int it = 0; it < 16; it++) {
                int row = it * 8 + wid * 2 + (lane >> 4);
                int cc = (lane & 15) * 8;
                *reinterpret_cast<uint4*>(Eb + (row0 + row) * MM + col0 + cc) =
                    *reinterpret_cast<uint4*>(&sv[row * RS + cc]);
            }
        } else {
            // EPI == 3: PV — divide by row sums, two 64-col halves
            constexpr int RSF = 68;
            float* svf = reinterpret_cast<float*>(smem + EPIOFF);
            float* s_inv = reinterpret_cast<float*>(smem + EPIOFF + 128 * RSF * 4);
            {
                const float4* pp = reinterpret_cast<const float4*>(
                    g_psum + ((long)bz * MM + row0 + tid) * 32);
                float s = 0.0f;
#pragma unroll
                for (int q = 0; q < 8; q++) {
                    float4 v = pp[q];
                    s += (v.x + v.y) + (v.z + v.w);
                }
                s_inv[tid] = 1.0f / s;
            }
            __syncthreads();
#pragma unroll
            for (int hh = 0; hh < 2; hh++) {
                if (wn == hh) {
#pragma unroll
                    for (int mt = 0; mt < 4; mt++) {
                        int l0 = wm * 64 + mt * 16 + g;
                        float inv0 = s_inv[l0];
                        float inv1 = s_inv[l0 + 8];
#pragma unroll
                        for (int nt = 0; nt < NT; nt++) {
                            int cl = nt * 8 + tg * 2;
                            *reinterpret_cast<float2*>(&svf[l0 * RSF + cl]) =
                                make_float2(acc[mt][nt][0] * inv0, acc[mt][nt][1] * inv0);
                            *reinterpret_cast<float2*>(&svf[(l0 + 8) * RSF + cl]) =
                                make_float2(acc[mt][nt][2] * inv1, acc[mt][nt][3] * inv1);
                        }
                    }
                }
                __syncthreads();
#pragma unroll
                for (int it = 0; it < 16; it++) {
                    int row = it * 8 + wid * 2 + (lane >> 4);
                    int cc = (lane & 15) * 4;
                    *reinterpret_cast<uint4*>(Cbase + (row0 + row) * ldc + col0 + hh * 64 + cc) =
                        *reinterpret_cast<uint4*>(&svf[row * RSF + cc]);
                }
                __syncthreads();
            }
        }

        curA = nxtA;
        curB = nxtB;
    }
}

// ---------------------------------------------------------------------------
// Launch. 4 kernels: prep, proj, scores, PV. Persistent grids.
// ---------------------------------------------------------------------------
extern "C" void kernel_launch(void* const* d_in, const int* in_sizes, int n_in,
                              void* d_out, int out_size) {
    (void)in_sizes; (void)n_in; (void)out_size;
    const float* x  = (const float*)d_in[0];
    const float* wq = (const float*)d_in[1];
    const float* wk = (const float*)d_in[2];
    const float* wv = (const float*)d_in[3];
    float* out = (float*)d_out;

    __half *xh, *wh, *Qh, *Kh, *VhT, *Eh;
    cudaGetSymbolAddress((void**)&xh, g_xh);
    cudaGetSymbolAddress((void**)&wh, g_wh);
    cudaGetSymbolAddress((void**)&Qh, g_Qh);
    cudaGetSymbolAddress((void**)&Kh, g_Kh);
    cudaGetSymbolAddress((void**)&VhT, g_VhT);
    cudaGetSymbolAddress((void**)&Eh, g_Eh);

    cudaFuncSetAttribute(mma_gemm_kernel<1>, cudaFuncAttributeMaxDynamicSharedMemorySize, GSMEM);
    cudaFuncSetAttribute(mma_gemm_kernel<2>, cudaFuncAttributeMaxDynamicSharedMemorySize, GSMEM);
    cudaFuncSetAttribute(mma_gemm_kernel<3>, cudaFuncAttributeMaxDynamicSharedMemorySize, GSMEM);

    // 0: prep (tables + cvt_x + cvt_w)
    prep_kernel<<<23552, 256>>>(x, wq, wk, wv);

    // 1: Merged QKV projection (persistent, 24x128 tiles, K=1024)
    mma_gemm_kernel<1><<<296, 128, GSMEM>>>(xh, wh, nullptr, DD, 0,
                                            0, 0, 0, 1.0f,
                                            24, 24 * 128, 3072);

    // 2: scores -> exp fp16 + psum (persistent, 16x16x8 tiles, K=1024)
    mma_gemm_kernel<2><<<296, 128, GSMEM>>>(Qh, Kh, nullptr, DD, 0,
                                            (long)MM * DD, (long)MM * DD, 0,
                                            0.03125f,
                                            16, 16 * 16, 2048);

    // 3: out = exp(S) @ V / rowsum (persistent, 8x16x8 tiles, K=2048)
    mma_gemm_kernel<3><<<296, 128, GSMEM>>>(Eh, VhT, out, MM, DD,
                                            (long)MM * MM, (long)DD * MM,
                                            (long)MM * DD, 1.0f,
                                            8, 8 * 16, 1024);
}